// round 7
// baseline (speedup 1.0000x reference)
#include <cuda_runtime.h>
#include <cuda_bf16.h>

typedef unsigned u32; typedef unsigned long long u64;
#define BB 64
#define SS 4096
#define DD 64
#define FF 256
#define INV_SIGMA 0.3535533905932738f
#define INV_SQRT_F 0.0625f

__device__ float    g_mean[BB * DD];
__device__ float    g_kvT [BB * DD * FF];   // [b][d][f]
__device__ float    g_ksum[BB * FF];
__device__ unsigned g_kmax[BB];

// ---------------- helpers ----------------------------------------------------
__device__ __forceinline__ u32 smem_u32(const void* p) {
    u32 a; asm("{ .reg .u64 t; cvta.to.shared.u64 t, %1; cvt.u32.u64 %0, t; }" : "=r"(a) : "l"(p));
    return a;
}
__device__ __forceinline__ void sts32(u32 a, u32 v) {
    asm volatile("st.shared.b32 [%0], %1;" :: "r"(a), "r"(v) : "memory");
}
__device__ __forceinline__ void split2(float a, float b, u32& hi, u32& lo) {
    u32 h; asm("cvt.rn.bf16x2.f32 %0,%1,%2;" : "=r"(h) : "f"(b), "f"(a));
    float ah = __uint_as_float(h << 16), bh = __uint_as_float(h & 0xffff0000u);
    float ar = a - ah, br = b - bh;
    asm("cvt.rn.bf16x2.f32 %0,%1,%2;" : "=r"(lo) : "f"(br), "f"(ar));
    hi = h;
}
__device__ __forceinline__ unsigned enc_max(float x) {
    unsigned b = __float_as_uint(x);
    return (b & 0x80000000u) ? ~b : (b | 0x80000000u);
}
__device__ __forceinline__ void ldsm4(u32 a, u32& r0, u32& r1, u32& r2, u32& r3) {
    asm volatile("ldmatrix.sync.aligned.m8n8.x4.shared.b16 {%0,%1,%2,%3}, [%4];"
                 : "=r"(r0), "=r"(r1), "=r"(r2), "=r"(r3) : "r"(a));
}
__device__ __forceinline__ void ldsm4t(u32 a, u32& r0, u32& r1, u32& r2, u32& r3) {
    asm volatile("ldmatrix.sync.aligned.m8n8.x4.trans.shared.b16 {%0,%1,%2,%3}, [%4];"
                 : "=r"(r0), "=r"(r1), "=r"(r2), "=r"(r3) : "r"(a));
}
__device__ __forceinline__ void ldsm2t(u32 a, u32& r0, u32& r1) {
    asm volatile("ldmatrix.sync.aligned.m8n8.x2.trans.shared.b16 {%0,%1}, [%2];"
                 : "=r"(r0), "=r"(r1) : "r"(a));
}
__device__ __forceinline__ void mma16816(float* c, u32 a0, u32 a1, u32 a2, u32 a3, u32 b0, u32 b1) {
    asm volatile("mma.sync.aligned.m16n8k16.row.col.f32.bf16.bf16.f32 "
                 "{%0,%1,%2,%3},{%4,%5,%6,%7},{%8,%9},{%0,%1,%2,%3};"
                 : "+f"(c[0]), "+f"(c[1]), "+f"(c[2]), "+f"(c[3])
                 : "r"(a0), "r"(a1), "r"(a2), "r"(a3), "r"(b0), "r"(b1));
}

// stage one 64-float row as bf16 hi(/lo) into pitch-144B tile at row r
__device__ __forceinline__ void stage_row(u32 hB, u32 lB, const float4* src, int r, float scale,
                                          const float* cen, float* nsq_out) {
    u32 rb = (u32)r * 144u;
    float nsq = 0.0f;
#pragma unroll
    for (int i = 0; i < 16; i++) {
        float4 x = src[i];
        float c0 = x.x * scale, c1 = x.y * scale, c2 = x.z * scale, c3 = x.w * scale;
        if (cen) { c0 -= cen[4*i]; c1 -= cen[4*i+1]; c2 -= cen[4*i+2]; c3 -= cen[4*i+3]; }
        nsq += c0*c0 + c1*c1 + c2*c2 + c3*c3;
        u32 h0, l0, h1, l1;
        split2(c0, c1, h0, l0); split2(c2, c3, h1, l1);
        sts32(hB + rb + i * 8u, h0); sts32(hB + rb + i * 8u + 4u, h1);
        if (lB) { sts32(lB + rb + i * 8u, l0); sts32(lB + rb + i * 8u + 4u, l1); }
    }
    if (nsq_out) *nsq_out = 0.5f * nsq;
}

// 2-mtile 1-pass GEMM (hi only)
template<int NT>
__device__ __forceinline__ void mma_h2(float (&acc)[2][NT][4], u32 aH, u32 bH,
                                       int nk, u32 ap, u32 bp) {
    const int lane = threadIdx.x & 31;
    const u32 aoff = (u32)(lane & 15) * ap + (u32)(lane >> 4) * 16u;
    const u32 boff = (u32)(lane & 15) * bp + (u32)(lane >> 4) * 16u;
    for (int kk = 0; kk < nk; kk++) {
        u32 a[2][4];
#pragma unroll
        for (int mt = 0; mt < 2; mt++)
            ldsm4(aH + aoff + (u32)mt * 16u * ap + (u32)kk * 32u,
                  a[mt][0], a[mt][1], a[mt][2], a[mt][3]);
#pragma unroll
        for (int ntp = 0; ntp < NT / 2; ntp++) {
            u32 h0, h1, h2, h3;
            ldsm4(bH + boff + (u32)ntp * 16u * bp + (u32)kk * 32u, h0, h1, h2, h3);
#pragma unroll
            for (int mt = 0; mt < 2; mt++) {
                mma16816(acc[mt][2*ntp],   a[mt][0], a[mt][1], a[mt][2], a[mt][3], h0, h2);
                mma16816(acc[mt][2*ntp+1], a[mt][0], a[mt][1], a[mt][2], a[mt][3], h1, h3);
            }
        }
    }
}

// 2-mtile fused hi/lo GEMM (HH + HL + LH)
template<int NT>
__device__ __forceinline__ void mma_hl2(float (&acc)[2][NT][4], u32 aH, u32 aL,
                                        u32 bH, u32 bL, int nk, u32 ap, u32 bp) {
    const int lane = threadIdx.x & 31;
    const u32 aoff = (u32)(lane & 15) * ap + (u32)(lane >> 4) * 16u;
    const u32 boff = (u32)(lane & 15) * bp + (u32)(lane >> 4) * 16u;
    for (int kk = 0; kk < nk; kk++) {
        u32 ah[2][4], al[2][4];
#pragma unroll
        for (int mt = 0; mt < 2; mt++) {
            ldsm4(aH + aoff + (u32)mt * 16u * ap + (u32)kk * 32u,
                  ah[mt][0], ah[mt][1], ah[mt][2], ah[mt][3]);
            ldsm4(aL + aoff + (u32)mt * 16u * ap + (u32)kk * 32u,
                  al[mt][0], al[mt][1], al[mt][2], al[mt][3]);
        }
#pragma unroll
        for (int ntp = 0; ntp < NT / 2; ntp++) {
            u32 h0, h1, h2, h3, l0, l1, l2, l3;
            ldsm4(bH + boff + (u32)ntp * 16u * bp + (u32)kk * 32u, h0, h1, h2, h3);
            ldsm4(bL + boff + (u32)ntp * 16u * bp + (u32)kk * 32u, l0, l1, l2, l3);
#pragma unroll
            for (int mt = 0; mt < 2; mt++) {
                mma16816(acc[mt][2*ntp],   ah[mt][0], ah[mt][1], ah[mt][2], ah[mt][3], h0, h2);
                mma16816(acc[mt][2*ntp],   ah[mt][0], ah[mt][1], ah[mt][2], ah[mt][3], l0, l2);
                mma16816(acc[mt][2*ntp],   al[mt][0], al[mt][1], al[mt][2], al[mt][3], h0, h2);
                mma16816(acc[mt][2*ntp+1], ah[mt][0], ah[mt][1], ah[mt][2], ah[mt][3], h1, h3);
                mma16816(acc[mt][2*ntp+1], ah[mt][0], ah[mt][1], ah[mt][2], ah[mt][3], l1, l3);
                mma16816(acc[mt][2*ntp+1], al[mt][0], al[mt][1], al[mt][2], al[mt][3], h1, h3);
            }
        }
    }
}

// ---------------- init + mean ------------------------------------------------
__global__ void init_kernel() {
    int i = blockIdx.x * 256 + threadIdx.x;
    if (i < BB * DD * FF) g_kvT[i] = 0.0f;
    if (i < BB * FF)      g_ksum[i] = 0.0f;
    if (i < BB * DD)      g_mean[i] = 0.0f;
    if (i < BB)           g_kmax[i] = 0x007FFFFFu;
}
__global__ void mean_kernel(const float* __restrict__ k) {
    const int b = blockIdx.x, p = blockIdx.y;
    const int d = threadIdx.x & 63, sub = threadIdx.x >> 6;
    const float* kp = k + (size_t)(b * SS + p * 1024) * DD;
    float s = 0.0f;
    for (int r = sub; r < 1024; r += 4) s += kp[r * DD + d];
    __shared__ float sm[4][DD];
    sm[sub][d] = s; __syncthreads();
    if (threadIdx.x < DD)
        atomicAdd(&g_mean[b * DD + threadIdx.x],
                  sm[0][threadIdx.x] + sm[1][threadIdx.x] + sm[2][threadIdx.x] + sm[3][threadIdx.x]);
}

// ---------------- kmax: max over Kc @ W^T (1-pass bf16; shift cancels exactly) -
#define KM_WH 0u
#define KM_KH 36864u
#define KM_ME 55296u
#define KM_SMEM (KM_ME + 256u)
__global__ void __launch_bounds__(256, 2)
kmax_kernel(const float* __restrict__ k, const float* __restrict__ w) {
    extern __shared__ __align__(16) char sm[];
    const u32 smb = smem_u32(sm);
    const int tid = threadIdx.x, wid = tid >> 5;
    const int wm = wid & 3, wn = wid >> 2;
    const int b = blockIdx.x, s0 = blockIdx.y * 128;
    float* meanc = (float*)(sm + KM_ME);
    if (tid < DD) meanc[tid] = g_mean[b * DD + tid] * (INV_SIGMA / (float)SS);
    __syncthreads();
    stage_row(smb + KM_WH, 0, (const float4*)(w + tid * DD), tid, 1.0f, 0, 0);
    if (tid < 128)
        stage_row(smb + KM_KH, 0, (const float4*)(k + (size_t)(b * SS + s0 + tid) * DD),
                  tid, INV_SIGMA, meanc, 0);
    __syncthreads();
    float mx = -3.0e38f;
    const u32 aB = smb + KM_KH + (u32)(wm * 32) * 144u;
    for (int c2 = 0; c2 < 2; c2++) {
        float acc[2][8][4];
#pragma unroll
        for (int mt = 0; mt < 2; mt++)
#pragma unroll
            for (int nt = 0; nt < 8; nt++)
#pragma unroll
                for (int j = 0; j < 4; j++) acc[mt][nt][j] = 0.0f;
        mma_h2<8>(acc, aB, smb + KM_WH + (u32)(wn * 128 + c2 * 64) * 144u, 4, 144u, 144u);
#pragma unroll
        for (int mt = 0; mt < 2; mt++)
#pragma unroll
            for (int nt = 0; nt < 8; nt++)
#pragma unroll
                for (int j = 0; j < 4; j++) mx = fmaxf(mx, acc[mt][nt][j]);
    }
    mx = fmaxf(mx, __shfl_xor_sync(~0u, mx, 16));
    mx = fmaxf(mx, __shfl_xor_sync(~0u, mx, 8));
    mx = fmaxf(mx, __shfl_xor_sync(~0u, mx, 4));
    mx = fmaxf(mx, __shfl_xor_sync(~0u, mx, 2));
    mx = fmaxf(mx, __shfl_xor_sync(~0u, mx, 1));
    if ((tid & 31) == 0) atomicMax(&g_kmax[b], enc_max(mx));
}

// ---------------- kv: KV[d,f] (+ksum) = (phi_k^T @ [V | 1])^T -----------------
// proj: warps (wm: 32 s-rows, wn: 64 f). gemm: warps (wm: 32 f-rows, wn: k-half),
// k-halves merged by the gmem atomicAdd epilogue.
#define KV_WH 0u
#define KV_WL 18432u
#define KV_KH 36864u
#define KV_KL 55296u
#define KV_PH 73728u
#define KV_PL 108544u
#define KV_VH 143360u
#define KV_VL 161792u
#define KV_ME 180224u
#define KV_NS 180480u
#define KV_SMEM (KV_NS + 512u)
__global__ void __launch_bounds__(256, 1)
kv_kernel(const float* __restrict__ k, const float* __restrict__ v, const float* __restrict__ w) {
    extern __shared__ __align__(16) char sm[];
    const u32 smb = smem_u32(sm);
    const int tid = threadIdx.x, wid = tid >> 5, lane = tid & 31;
    const int wm = wid & 3, wn = wid >> 2;
    const int b = blockIdx.x, F0 = blockIdx.y * 128;
    float* meanc = (float*)(sm + KV_ME);
    float* nsqs  = (float*)(sm + KV_NS);
    if (tid < DD) meanc[tid] = g_mean[b * DD + tid] * (INV_SIGMA / (float)SS);
    const float gmax = (g_kmax[b] & 0x80000000u) ? __uint_as_float(g_kmax[b] & 0x7FFFFFFFu)
                                                 : __uint_as_float(~g_kmax[b]);
    if (tid < 128)
        stage_row(smb + KV_WH, smb + KV_WL, (const float4*)(w + (F0 + tid) * DD), tid, 1.0f, 0, 0);
    __syncthreads();

    float kva[2][9][4];
#pragma unroll
    for (int mt = 0; mt < 2; mt++)
#pragma unroll
        for (int nt = 0; nt < 9; nt++)
#pragma unroll
            for (int j = 0; j < 4; j++) kva[mt][nt][j] = 0.0f;

    for (int t = 0; t < 4; t++) {
        const int s0 = (blockIdx.z * 4 + t) * 128;
        if (tid < 128) {       // stage K rows (hi/lo, pitch 144)
            float nsq;
            stage_row(smb + KV_KH, smb + KV_KL,
                      (const float4*)(k + (size_t)(b * SS + s0 + tid) * DD), tid, INV_SIGMA, meanc, &nsq);
            nsqs[tid] = nsq;
        } else {               // stage V row [s][72] + ones cols (coalesced)
            const int sv = tid - 128;
            const float4* vr = (const float4*)(v + (size_t)(b * SS + s0 + sv) * DD);
            const u32 rb = (u32)sv * 144u;
#pragma unroll
            for (int i = 0; i < 16; i++) {
                float4 x = vr[i];
                u32 h0, l0, h1, l1;
                split2(x.x, x.y, h0, l0); split2(x.z, x.w, h1, l1);
                sts32(smb + KV_VH + rb + i * 8u,      h0);
                sts32(smb + KV_VH + rb + i * 8u + 4u, h1);
                sts32(smb + KV_VL + rb + i * 8u,      l0);
                sts32(smb + KV_VL + rb + i * 8u + 4u, l1);
            }
#pragma unroll
            for (int j = 0; j < 4; j++) {
                sts32(smb + KV_VH + rb + 128u + 4u * j, 0x3F803F80u);
                sts32(smb + KV_VL + rb + 128u + 4u * j, 0u);
            }
        }
        __syncthreads();
        // proj: warp (wm: 32 s-rows, wn: 64 f); fused 3-pass hi/lo
        {
            float acc[2][8][4];
#pragma unroll
            for (int mt = 0; mt < 2; mt++)
#pragma unroll
                for (int nt = 0; nt < 8; nt++)
#pragma unroll
                    for (int j = 0; j < 4; j++) acc[mt][nt][j] = 0.0f;
            mma_hl2<8>(acc, smb + KV_KH + (u32)(wm * 32) * 144u,
                            smb + KV_KL + (u32)(wm * 32) * 144u,
                            smb + KV_WH + (u32)(wn * 64) * 144u,
                            smb + KV_WL + (u32)(wn * 64) * 144u, 4, 144u, 144u);
            // exp + store phi natural [s][f] pitch 272
            float n[4];
#pragma unroll
            for (int j = 0; j < 4; j++)
                n[j] = nsqs[wm * 32 + (lane >> 2) + j * 8] + gmax;
#pragma unroll
            for (int nt = 0; nt < 8; nt++) {
                const int f = wn * 64 + nt * 8 + (lane & 3) * 2;
#pragma unroll
                for (int mt = 0; mt < 2; mt++) {
                    const int rb = wm * 32 + (lane >> 2) + mt * 16;
                    float p00 = __expf(acc[mt][nt][0] - n[2*mt])     * INV_SQRT_F;
                    float p01 = __expf(acc[mt][nt][1] - n[2*mt])     * INV_SQRT_F;
                    float p10 = __expf(acc[mt][nt][2] - n[2*mt + 1]) * INV_SQRT_F;
                    float p11 = __expf(acc[mt][nt][3] - n[2*mt + 1]) * INV_SQRT_F;
                    u32 hi, lo;
                    split2(p00, p01, hi, lo);
                    sts32(smb + KV_PH + (u32)rb * 272u + 2u * f, hi);
                    sts32(smb + KV_PL + (u32)rb * 272u + 2u * f, lo);
                    split2(p10, p11, hi, lo);
                    sts32(smb + KV_PH + (u32)(rb + 8) * 272u + 2u * f, hi);
                    sts32(smb + KV_PL + (u32)(rb + 8) * 272u + 2u * f, lo);
                }
            }
        }
        __syncthreads();
        // kv gemm: warp (wm: 32 f-rows, wn: 64-s k-half); trans loads
        {
            const u32 aoff = ((u32)(lane & 7) + (u32)((lane >> 4) & 1) * 8u) * 272u +
                             (u32)((lane >> 3) & 1) * 16u + (u32)(wm * 64) +
                             (u32)(wn * 64) * 272u;
            const u32 boff = ((u32)(lane & 7) + (u32)((lane >> 3) & 1) * 8u) * 144u +
                             (u32)((lane >> 4) & 1) * 16u + (u32)(wn * 64) * 144u;
            const u32 b2off = ((u32)(lane & 7) + (u32)((lane >> 3) & 1) * 8u) * 144u + 128u +
                              (u32)(wn * 64) * 144u;
            const u32 PHb = smb + KV_PH, PLb = smb + KV_PL;
            const u32 VHb = smb + KV_VH, VLb = smb + KV_VL;
            for (int kk = 0; kk < 4; kk++) {
                const u32 ka = (u32)kk * 16u * 272u, kb = (u32)kk * 16u * 144u;
                u32 ah[2][4], al[2][4];
#pragma unroll
                for (int mt = 0; mt < 2; mt++) {
                    ldsm4t(PHb + aoff + (u32)(mt * 32) + ka, ah[mt][0], ah[mt][1], ah[mt][2], ah[mt][3]);
                    ldsm4t(PLb + aoff + (u32)(mt * 32) + ka, al[mt][0], al[mt][1], al[mt][2], al[mt][3]);
                }
#pragma unroll
                for (int ntp = 0; ntp < 4; ntp++) {
                    u32 h0, h1, h2, h3, l0, l1, l2, l3;
                    ldsm4t(VHb + boff + (u32)ntp * 32u + kb, h0, h1, h2, h3);
                    ldsm4t(VLb + boff + (u32)ntp * 32u + kb, l0, l1, l2, l3);
#pragma unroll
                    for (int mt = 0; mt < 2; mt++) {
                        mma16816(kva[mt][2*ntp],   ah[mt][0], ah[mt][1], ah[mt][2], ah[mt][3], h0, h1);
                        mma16816(kva[mt][2*ntp],   ah[mt][0], ah[mt][1], ah[mt][2], ah[mt][3], l0, l1);
                        mma16816(kva[mt][2*ntp],   al[mt][0], al[mt][1], al[mt][2], al[mt][3], h0, h1);
                        mma16816(kva[mt][2*ntp+1], ah[mt][0], ah[mt][1], ah[mt][2], ah[mt][3], h2, h3);
                        mma16816(kva[mt][2*ntp+1], ah[mt][0], ah[mt][1], ah[mt][2], ah[mt][3], l2, l3);
                        mma16816(kva[mt][2*ntp+1], al[mt][0], al[mt][1], al[mt][2], al[mt][3], h2, h3);
                    }
                }
                u32 o0, o1;
                ldsm2t(VHb + b2off + kb, o0, o1);
#pragma unroll
                for (int mt = 0; mt < 2; mt++) {
                    mma16816(kva[mt][8], ah[mt][0], ah[mt][1], ah[mt][2], ah[mt][3], o0, o1);
                    mma16816(kva[mt][8], al[mt][0], al[mt][1], al[mt][2], al[mt][3], o0, o1);
                }
            }
        }
        __syncthreads();
    }
    // epilogue: scatter KV^T and ksum (k-halves merge via atomics)
#pragma unroll
    for (int mt = 0; mt < 2; mt++) {
        const int f0 = F0 + wm * 32 + (lane >> 2) + mt * 16;
#pragma unroll
        for (int nt = 0; nt < 9; nt++) {
            const int d = nt * 8 + (lane & 3) * 2;
            if (nt < 8) {
                atomicAdd(g_kvT + ((size_t)b * DD + d)     * FF + f0,      kva[mt][nt][0]);
                atomicAdd(g_kvT + ((size_t)b * DD + d + 1) * FF + f0,      kva[mt][nt][1]);
                atomicAdd(g_kvT + ((size_t)b * DD + d)     * FF + f0 + 8,  kva[mt][nt][2]);
                atomicAdd(g_kvT + ((size_t)b * DD + d + 1) * FF + f0 + 8,  kva[mt][nt][3]);
            } else if ((lane & 3) == 0) {
                atomicAdd(g_ksum + b * FF + f0,     kva[mt][nt][0]);
                atomicAdd(g_ksum + b * FF + f0 + 8, kva[mt][nt][2]);
            }
        }
    }
}

// ---------------- out: phi_q @ KV^T / deno ------------------------------------
// proj: warps (wm: 32 s-rows, wn: 32 f of the 64-f chunk).
// gemm: warps (wm: 32 s-rows, wn: 32-f k-half) — halves reduced via smem scratch.
#define OU_WH 0u
#define OU_WL 36864u
#define OU_QH 73728u
#define OU_QL 92160u
#define OU_PH 110592u
#define OU_PL 129024u
#define OU_KVH 147456u
#define OU_KVL 181248u
#define OU_KS 215040u
#define OU_NS 216064u
#define OU_RM 216576u
#define OU_DE 217600u
#define OU_SMEM (OU_DE + 1024u)
__global__ void __launch_bounds__(256, 1)
out_kernel(const float* __restrict__ q, const float* __restrict__ w, float* __restrict__ out) {
    extern __shared__ __align__(16) char sm[];
    const u32 smb = smem_u32(sm);
    const int tid = threadIdx.x, wid = tid >> 5, lane = tid & 31;
    const int wm = wid & 3, wn = wid >> 2;
    const int b = blockIdx.x, s0 = blockIdx.y * 128;
    float* ksum_s = (float*)(sm + OU_KS);
    float* nsqs   = (float*)(sm + OU_NS);
    float* rm2    = (float*)(sm + OU_RM);   // [2][128]
    float* dn2    = (float*)(sm + OU_DE);   // [2][128]
    float* scr    = (float*)(sm + OU_PH);   // overlay: [128][66] f32 reduction scratch
    ksum_s[tid] = g_ksum[b * FF + tid];
    stage_row(smb + OU_WH, smb + OU_WL, (const float4*)(w + tid * DD), tid, 1.0f, 0, 0);
    if (tid < 128) {
        float nsq;
        stage_row(smb + OU_QH, smb + OU_QL, (const float4*)(q + (size_t)(b * SS + s0 + tid) * DD),
                  tid, INV_SIGMA, 0, &nsq);
        nsqs[tid] = nsq;
    } else {   // KV^T tile [d][f] hi/lo, pitch 528
        const int d = (tid - 128) >> 1, half = tid & 1;
        const float* src = g_kvT + (size_t)b * DD * FF + d * FF + half * 128;
        const u32 rb = (u32)d * 528u + (u32)half * 256u;
#pragma unroll 8
        for (int j = 0; j < 64; j++) {
            u32 hi, lo;
            split2(src[2*j], src[2*j+1], hi, lo);
            sts32(smb + OU_KVH + rb + 4u * j, hi);
            sts32(smb + OU_KVL + rb + 4u * j, lo);
        }
    }
    __syncthreads();

    const u32 qH = smb + OU_QH + (u32)(wm * 32) * 144u;
    const u32 qL = smb + OU_QL + (u32)(wm * 32) * 144u;
    // pass 1: row max (1-pass bf16; per-row shift cancels in num/deno)
    {
        float mx[4] = {-3.0e38f, -3.0e38f, -3.0e38f, -3.0e38f};
        for (int c2 = 0; c2 < 2; c2++) {
            float acc[2][8][4];
#pragma unroll
            for (int mt = 0; mt < 2; mt++)
#pragma unroll
                for (int nt = 0; nt < 8; nt++)
#pragma unroll
                    for (int j = 0; j < 4; j++) acc[mt][nt][j] = 0.0f;
            mma_h2<8>(acc, qH, smb + OU_WH + (u32)(wn * 128 + c2 * 64) * 144u, 4, 144u, 144u);
#pragma unroll
            for (int mt = 0; mt < 2; mt++)
#pragma unroll
                for (int nt = 0; nt < 8; nt++) {
                    mx[2*mt]   = fmaxf(mx[2*mt],   fmaxf(acc[mt][nt][0], acc[mt][nt][1]));
                    mx[2*mt+1] = fmaxf(mx[2*mt+1], fmaxf(acc[mt][nt][2], acc[mt][nt][3]));
                }
        }
#pragma unroll
        for (int j = 0; j < 4; j++) {
            mx[j] = fmaxf(mx[j], __shfl_xor_sync(~0u, mx[j], 1));
            mx[j] = fmaxf(mx[j], __shfl_xor_sync(~0u, mx[j], 2));
        }
        if ((lane & 3) == 0)
#pragma unroll
            for (int j = 0; j < 4; j++)
                rm2[wn * 128 + wm * 32 + (lane >> 2) + j * 8] = mx[j];
    }
    __syncthreads();

    float n[4], dp[4] = {0.f, 0.f, 0.f, 0.f};
#pragma unroll
    for (int j = 0; j < 4; j++) {
        const int r = wm * 32 + (lane >> 2) + j * 8;
        n[j] = nsqs[r] + fmaxf(rm2[r], rm2[128 + r]);
    }

    float oacc[2][8][4];
#pragma unroll
    for (int mt = 0; mt < 2; mt++)
#pragma unroll
        for (int nt = 0; nt < 8; nt++)
#pragma unroll
            for (int j = 0; j < 4; j++) oacc[mt][nt][j] = 0.0f;

    for (int ch = 0; ch < 4; ch++) {
        float acc[2][4][4];
#pragma unroll
        for (int mt = 0; mt < 2; mt++)
#pragma unroll
            for (int nt = 0; nt < 4; nt++)
#pragma unroll
                for (int j = 0; j < 4; j++) acc[mt][nt][j] = 0.0f;
        mma_hl2<4>(acc, qH, qL, smb + OU_WH + (u32)(ch * 64 + wn * 32) * 144u,
                   smb + OU_WL + (u32)(ch * 64 + wn * 32) * 144u, 4, 144u, 144u);
#pragma unroll
        for (int nt = 0; nt < 4; nt++) {
            const int fl = wn * 32 + nt * 8 + (lane & 3) * 2;
            const int fg = ch * 64 + fl;
            const float ks0 = ksum_s[fg], ks1 = ksum_s[fg + 1];
#pragma unroll
            for (int mt = 0; mt < 2; mt++) {
                const int rb = wm * 32 + (lane >> 2) + mt * 16;
                float p00 = __expf(acc[mt][nt][0] - n[2*mt])     * INV_SQRT_F;
                float p01 = __expf(acc[mt][nt][1] - n[2*mt])     * INV_SQRT_F;
                float p10 = __expf(acc[mt][nt][2] - n[2*mt + 1]) * INV_SQRT_F;
                float p11 = __expf(acc[mt][nt][3] - n[2*mt + 1]) * INV_SQRT_F;
                dp[2*mt]     += p00 * ks0 + p01 * ks1;
                dp[2*mt + 1] += p10 * ks0 + p11 * ks1;
                u32 hi, lo;
                split2(p00, p01, hi, lo);
                sts32(smb + OU_PH + (u32)rb * 144u + 2u * fl, hi);
                sts32(smb + OU_PL + (u32)rb * 144u + 2u * fl, lo);
                split2(p10, p11, hi, lo);
                sts32(smb + OU_PH + (u32)(rb + 8) * 144u + 2u * fl, hi);
                sts32(smb + OU_PL + (u32)(rb + 8) * 144u + 2u * fl, lo);
            }
        }
        __syncthreads();
        // gemm: warp (wm rows, wn 32-f k-half of this chunk)
        mma_hl2<8>(oacc, smb + OU_PH + (u32)(wm * 32) * 144u + (u32)(wn * 64),
                         smb + OU_PL + (u32)(wm * 32) * 144u + (u32)(wn * 64),
                         smb + OU_KVH + (u32)(ch * 128 + wn * 64),
                         smb + OU_KVL + (u32)(ch * 128 + wn * 64), 2, 144u, 528u);
        __syncthreads();
    }
    // deno partials
#pragma unroll
    for (int j = 0; j < 4; j++) {
        dp[j] += __shfl_xor_sync(~0u, dp[j], 1);
        dp[j] += __shfl_xor_sync(~0u, dp[j], 2);
    }
    if ((lane & 3) == 0)
#pragma unroll
        for (int j = 0; j < 4; j++)
            dn2[wn * 128 + wm * 32 + (lane >> 2) + j * 8] = dp[j];
    __syncthreads();
    // reduce wn k-halves: wn1 spills to scratch (overlays dead phi buffer)
    if (wn == 1) {
#pragma unroll
        for (int nt = 0; nt < 8; nt++) {
            const int d = nt * 8 + (lane & 3) * 2;
#pragma unroll
            for (int mt = 0; mt < 2; mt++) {
                const int rb = wm * 32 + (lane >> 2) + mt * 16;
                *(float2*)(scr + rb * 66 + d)       = make_float2(oacc[mt][nt][0], oacc[mt][nt][1]);
                *(float2*)(scr + (rb + 8) * 66 + d) = make_float2(oacc[mt][nt][2], oacc[mt][nt][3]);
            }
        }
    }
    __syncthreads();
    if (wn == 0) {
        float inv[4];
#pragma unroll
        for (int j = 0; j < 4; j++) {
            const int r = wm * 32 + (lane >> 2) + j * 8;
            inv[j] = 1.0f / fmaxf(dn2[r] + dn2[128 + r], 1e-4f);
        }
#pragma unroll
        for (int nt = 0; nt < 8; nt++) {
            const int d = nt * 8 + (lane & 3) * 2;
#pragma unroll
            for (int mt = 0; mt < 2; mt++) {
                const int rb = wm * 32 + (lane >> 2) + mt * 16;
                float2 s0v = *(const float2*)(scr + rb * 66 + d);
                float2 s1v = *(const float2*)(scr + (rb + 8) * 66 + d);
                *(float2*)(out + (size_t)(b * SS + s0 + rb) * DD + d) =
                    make_float2((oacc[mt][nt][0] + s0v.x) * inv[2*mt],
                                (oacc[mt][nt][1] + s0v.y) * inv[2*mt]);
                *(float2*)(out + (size_t)(b * SS + s0 + rb + 8) * DD + d) =
                    make_float2((oacc[mt][nt][2] + s1v.x) * inv[2*mt + 1],
                                (oacc[mt][nt][3] + s1v.y) * inv[2*mt + 1]);
            }
        }
    }
}

// ---------------- launch ------------------------------------------------------
extern "C" void kernel_launch(void* const* d_in, const int* in_sizes, int n_in,
                              void* d_out, int out_size) {
    const float* q = (const float*)d_in[0];
    const float* k = (const float*)d_in[1];
    const float* v = (const float*)d_in[2];
    const float* w = (const float*)d_in[3];
    float* out = (float*)d_out;
    cudaFuncSetAttribute(kmax_kernel, cudaFuncAttributeMaxDynamicSharedMemorySize, KM_SMEM);
    cudaFuncSetAttribute(kv_kernel,   cudaFuncAttributeMaxDynamicSharedMemorySize, KV_SMEM);
    cudaFuncSetAttribute(out_kernel,  cudaFuncAttributeMaxDynamicSharedMemorySize, OU_SMEM);
    init_kernel<<<(BB * DD * FF + 255) / 256, 256>>>();
    mean_kernel<<<dim3(BB, 4), 256>>>(k);
    kmax_kernel<<<dim3(BB, SS / 128), 256, KM_SMEM>>>(k, w);
    kv_kernel<<<dim3(BB, 2, 8), 256, KV_SMEM>>>(k, v, w);
    out_kernel<<<dim3(BB, SS / 128), 256, OU_SMEM>>>(q, w, out);
}

// round 8
// speedup vs baseline: 1.1380x; 1.1380x over previous
#include <cuda_runtime.h>
#include <cuda_bf16.h>

typedef unsigned u32; typedef unsigned long long u64;
#define BB 64
#define SS 4096
#define DD 64
#define FF 256
#define INV_SIGMA 0.3535533905932738f
#define INV_SQRT_F 0.0625f

__device__ float g_mean[BB * DD];
__device__ float g_kvT [BB * DD * FF];   // [b][d][f]
__device__ float g_ksum[BB * FF];

// ---------------- helpers ----------------------------------------------------
__device__ __forceinline__ u32 smem_u32(const void* p) {
    u32 a; asm("{ .reg .u64 t; cvta.to.shared.u64 t, %1; cvt.u32.u64 %0, t; }" : "=r"(a) : "l"(p));
    return a;
}
__device__ __forceinline__ void sts32(u32 a, u32 v) {
    asm volatile("st.shared.b32 [%0], %1;" :: "r"(a), "r"(v) : "memory");
}
__device__ __forceinline__ void split2(float a, float b, u32& hi, u32& lo) {
    u32 h; asm("cvt.rn.bf16x2.f32 %0,%1,%2;" : "=r"(h) : "f"(b), "f"(a));
    float ah = __uint_as_float(h << 16), bh = __uint_as_float(h & 0xffff0000u);
    float ar = a - ah, br = b - bh;
    asm("cvt.rn.bf16x2.f32 %0,%1,%2;" : "=r"(lo) : "f"(br), "f"(ar));
    hi = h;
}
__device__ __forceinline__ void ldsm4(u32 a, u32& r0, u32& r1, u32& r2, u32& r3) {
    asm volatile("ldmatrix.sync.aligned.m8n8.x4.shared.b16 {%0,%1,%2,%3}, [%4];"
                 : "=r"(r0), "=r"(r1), "=r"(r2), "=r"(r3) : "r"(a));
}
__device__ __forceinline__ void ldsm4t(u32 a, u32& r0, u32& r1, u32& r2, u32& r3) {
    asm volatile("ldmatrix.sync.aligned.m8n8.x4.trans.shared.b16 {%0,%1,%2,%3}, [%4];"
                 : "=r"(r0), "=r"(r1), "=r"(r2), "=r"(r3) : "r"(a));
}
__device__ __forceinline__ void ldsm2t(u32 a, u32& r0, u32& r1) {
    asm volatile("ldmatrix.sync.aligned.m8n8.x2.trans.shared.b16 {%0,%1}, [%2];"
                 : "=r"(r0), "=r"(r1) : "r"(a));
}
__device__ __forceinline__ void mma16816(float* c, u32 a0, u32 a1, u32 a2, u32 a3, u32 b0, u32 b1) {
    asm volatile("mma.sync.aligned.m16n8k16.row.col.f32.bf16.bf16.f32 "
                 "{%0,%1,%2,%3},{%4,%5,%6,%7},{%8,%9},{%0,%1,%2,%3};"
                 : "+f"(c[0]), "+f"(c[1]), "+f"(c[2]), "+f"(c[3])
                 : "r"(a0), "r"(a1), "r"(a2), "r"(a3), "r"(b0), "r"(b1));
}

// stage one 64-float row as bf16 hi(/lo) into pitch-144B tile at row r
__device__ __forceinline__ void stage_row(u32 hB, u32 lB, const float4* src, int r, float scale,
                                          const float* cen, float* nsq_out) {
    u32 rb = (u32)r * 144u;
    float nsq = 0.0f;
#pragma unroll
    for (int i = 0; i < 16; i++) {
        float4 x = src[i];
        float c0 = x.x * scale, c1 = x.y * scale, c2 = x.z * scale, c3 = x.w * scale;
        if (cen) { c0 -= cen[4*i]; c1 -= cen[4*i+1]; c2 -= cen[4*i+2]; c3 -= cen[4*i+3]; }
        if (nsq_out) nsq += c0*c0 + c1*c1 + c2*c2 + c3*c3;
        u32 h0, l0, h1, l1;
        split2(c0, c1, h0, l0); split2(c2, c3, h1, l1);
        sts32(hB + rb + i * 8u, h0); sts32(hB + rb + i * 8u + 4u, h1);
        if (lB) { sts32(lB + rb + i * 8u, l0); sts32(lB + rb + i * 8u + 4u, l1); }
    }
    if (nsq_out) *nsq_out = 0.5f * nsq;
}

// 2-mtile fused hi/lo GEMM (HH + HL + LH)
template<int NT>
__device__ __forceinline__ void mma_hl2(float (&acc)[2][NT][4], u32 aH, u32 aL,
                                        u32 bH, u32 bL, int nk, u32 ap, u32 bp) {
    const int lane = threadIdx.x & 31;
    const u32 aoff = (u32)(lane & 15) * ap + (u32)(lane >> 4) * 16u;
    const u32 boff = (u32)(lane & 15) * bp + (u32)(lane >> 4) * 16u;
    for (int kk = 0; kk < nk; kk++) {
        u32 ah[2][4], al[2][4];
#pragma unroll
        for (int mt = 0; mt < 2; mt++) {
            ldsm4(aH + aoff + (u32)mt * 16u * ap + (u32)kk * 32u,
                  ah[mt][0], ah[mt][1], ah[mt][2], ah[mt][3]);
            ldsm4(aL + aoff + (u32)mt * 16u * ap + (u32)kk * 32u,
                  al[mt][0], al[mt][1], al[mt][2], al[mt][3]);
        }
#pragma unroll
        for (int ntp = 0; ntp < NT / 2; ntp++) {
            u32 h0, h1, h2, h3, l0, l1, l2, l3;
            ldsm4(bH + boff + (u32)ntp * 16u * bp + (u32)kk * 32u, h0, h1, h2, h3);
            ldsm4(bL + boff + (u32)ntp * 16u * bp + (u32)kk * 32u, l0, l1, l2, l3);
#pragma unroll
            for (int mt = 0; mt < 2; mt++) {
                mma16816(acc[mt][2*ntp],   ah[mt][0], ah[mt][1], ah[mt][2], ah[mt][3], h0, h2);
                mma16816(acc[mt][2*ntp],   ah[mt][0], ah[mt][1], ah[mt][2], ah[mt][3], l0, l2);
                mma16816(acc[mt][2*ntp],   al[mt][0], al[mt][1], al[mt][2], al[mt][3], h0, h2);
                mma16816(acc[mt][2*ntp+1], ah[mt][0], ah[mt][1], ah[mt][2], ah[mt][3], h1, h3);
                mma16816(acc[mt][2*ntp+1], ah[mt][0], ah[mt][1], ah[mt][2], ah[mt][3], l1, l3);
                mma16816(acc[mt][2*ntp+1], al[mt][0], al[mt][1], al[mt][2], al[mt][3], h1, h3);
            }
        }
    }
}

// ---------------- init + mean ------------------------------------------------
__global__ void init_kernel() {
    int i = blockIdx.x * 256 + threadIdx.x;
    if (i < BB * DD * FF) g_kvT[i] = 0.0f;
    if (i < BB * FF)      g_ksum[i] = 0.0f;
    if (i < BB * DD)      g_mean[i] = 0.0f;
}
__global__ void mean_kernel(const float* __restrict__ k) {
    const int b = blockIdx.x, p = blockIdx.y;
    const int d = threadIdx.x & 63, sub = threadIdx.x >> 6;
    const float* kp = k + (size_t)(b * SS + p * 1024) * DD;
    float s = 0.0f;
    for (int r = sub; r < 1024; r += 4) s += kp[r * DD + d];
    __shared__ float sm[4][DD];
    sm[sub][d] = s; __syncthreads();
    if (threadIdx.x < DD)
        atomicAdd(&g_mean[b * DD + threadIdx.x],
                  sm[0][threadIdx.x] + sm[1][threadIdx.x] + sm[2][threadIdx.x] + sm[3][threadIdx.x]);
}

// ---------------- kv: KV[d,f] (+ksum) = (phi_k^T @ [V | 1])^T -----------------
// NOTE: no global k-max — the e^{-gmax} factor cancels exactly between
// numerator (phi_q @ KV) and denominator (phi_q @ ksum); fp32 range verified.
#define KV_WH 0u
#define KV_WL 18432u
#define KV_KH 36864u
#define KV_KL 55296u
#define KV_PH 73728u
#define KV_PL 108544u
#define KV_VH 143360u
#define KV_VL 161792u
#define KV_ME 180224u
#define KV_NS 180480u
#define KV_SMEM (KV_NS + 512u)
__global__ void __launch_bounds__(256, 1)
kv_kernel(const float* __restrict__ k, const float* __restrict__ v, const float* __restrict__ w) {
    extern __shared__ __align__(16) char sm[];
    const u32 smb = smem_u32(sm);
    const int tid = threadIdx.x, wid = tid >> 5, lane = tid & 31;
    const int wm = wid & 3, wn = wid >> 2;
    const int b = blockIdx.x, F0 = blockIdx.y * 128;
    float* meanc = (float*)(sm + KV_ME);
    float* nsqs  = (float*)(sm + KV_NS);
    if (tid < DD) meanc[tid] = g_mean[b * DD + tid] * (INV_SIGMA / (float)SS);
    if (tid < 128)
        stage_row(smb + KV_WH, smb + KV_WL, (const float4*)(w + (F0 + tid) * DD), tid, 1.0f, 0, 0);
    __syncthreads();

    float kva[2][9][4];
#pragma unroll
    for (int mt = 0; mt < 2; mt++)
#pragma unroll
        for (int nt = 0; nt < 9; nt++)
#pragma unroll
            for (int j = 0; j < 4; j++) kva[mt][nt][j] = 0.0f;

    for (int t = 0; t < 4; t++) {
        const int s0 = (blockIdx.z * 4 + t) * 128;
        if (tid < 128) {       // stage K rows (hi/lo, pitch 144)
            float nsq;
            stage_row(smb + KV_KH, smb + KV_KL,
                      (const float4*)(k + (size_t)(b * SS + s0 + tid) * DD), tid, INV_SIGMA, meanc, &nsq);
            nsqs[tid] = nsq;
        } else {               // stage V row [s][72] + ones cols (coalesced)
            const int sv = tid - 128;
            const float4* vr = (const float4*)(v + (size_t)(b * SS + s0 + sv) * DD);
            const u32 rb = (u32)sv * 144u;
#pragma unroll
            for (int i = 0; i < 16; i++) {
                float4 x = vr[i];
                u32 h0, l0, h1, l1;
                split2(x.x, x.y, h0, l0); split2(x.z, x.w, h1, l1);
                sts32(smb + KV_VH + rb + i * 8u,      h0);
                sts32(smb + KV_VH + rb + i * 8u + 4u, h1);
                sts32(smb + KV_VL + rb + i * 8u,      l0);
                sts32(smb + KV_VL + rb + i * 8u + 4u, l1);
            }
#pragma unroll
            for (int j = 0; j < 4; j++) {
                sts32(smb + KV_VH + rb + 128u + 4u * j, 0x3F803F80u);
                sts32(smb + KV_VL + rb + 128u + 4u * j, 0u);
            }
        }
        __syncthreads();
        // proj: warp (wm: 32 s-rows, wn: 64 f); fused 3-pass hi/lo
        {
            float acc[2][8][4];
#pragma unroll
            for (int mt = 0; mt < 2; mt++)
#pragma unroll
                for (int nt = 0; nt < 8; nt++)
#pragma unroll
                    for (int j = 0; j < 4; j++) acc[mt][nt][j] = 0.0f;
            mma_hl2<8>(acc, smb + KV_KH + (u32)(wm * 32) * 144u,
                            smb + KV_KL + (u32)(wm * 32) * 144u,
                            smb + KV_WH + (u32)(wn * 64) * 144u,
                            smb + KV_WL + (u32)(wn * 64) * 144u, 4, 144u, 144u);
            // exp + store phi natural [s][f] pitch 272
            float n[4];
#pragma unroll
            for (int j = 0; j < 4; j++)
                n[j] = nsqs[wm * 32 + (lane >> 2) + j * 8];
#pragma unroll
            for (int nt = 0; nt < 8; nt++) {
                const int f = wn * 64 + nt * 8 + (lane & 3) * 2;
#pragma unroll
                for (int mt = 0; mt < 2; mt++) {
                    const int rb = wm * 32 + (lane >> 2) + mt * 16;
                    float p00 = __expf(acc[mt][nt][0] - n[2*mt])     * INV_SQRT_F;
                    float p01 = __expf(acc[mt][nt][1] - n[2*mt])     * INV_SQRT_F;
                    float p10 = __expf(acc[mt][nt][2] - n[2*mt + 1]) * INV_SQRT_F;
                    float p11 = __expf(acc[mt][nt][3] - n[2*mt + 1]) * INV_SQRT_F;
                    u32 hi, lo;
                    split2(p00, p01, hi, lo);
                    sts32(smb + KV_PH + (u32)rb * 272u + 2u * f, hi);
                    sts32(smb + KV_PL + (u32)rb * 272u + 2u * f, lo);
                    split2(p10, p11, hi, lo);
                    sts32(smb + KV_PH + (u32)(rb + 8) * 272u + 2u * f, hi);
                    sts32(smb + KV_PL + (u32)(rb + 8) * 272u + 2u * f, lo);
                }
            }
        }
        __syncthreads();
        // kv gemm: warp (wm: 32 f-rows, wn: 64-s k-half); trans loads
        {
            const u32 aoff = ((u32)(lane & 7) + (u32)((lane >> 4) & 1) * 8u) * 272u +
                             (u32)((lane >> 3) & 1) * 16u + (u32)(wm * 64) +
                             (u32)(wn * 64) * 272u;
            const u32 boff = ((u32)(lane & 7) + (u32)((lane >> 3) & 1) * 8u) * 144u +
                             (u32)((lane >> 4) & 1) * 16u + (u32)(wn * 64) * 144u;
            const u32 b2off = ((u32)(lane & 7) + (u32)((lane >> 3) & 1) * 8u) * 144u + 128u +
                              (u32)(wn * 64) * 144u;
            const u32 PHb = smb + KV_PH, PLb = smb + KV_PL;
            const u32 VHb = smb + KV_VH, VLb = smb + KV_VL;
            for (int kk = 0; kk < 4; kk++) {
                const u32 ka = (u32)kk * 16u * 272u, kb = (u32)kk * 16u * 144u;
                u32 ah[2][4], al[2][4];
#pragma unroll
                for (int mt = 0; mt < 2; mt++) {
                    ldsm4t(PHb + aoff + (u32)(mt * 32) + ka, ah[mt][0], ah[mt][1], ah[mt][2], ah[mt][3]);
                    ldsm4t(PLb + aoff + (u32)(mt * 32) + ka, al[mt][0], al[mt][1], al[mt][2], al[mt][3]);
                }
#pragma unroll
                for (int ntp = 0; ntp < 4; ntp++) {
                    u32 h0, h1, h2, h3, l0, l1, l2, l3;
                    ldsm4t(VHb + boff + (u32)ntp * 32u + kb, h0, h1, h2, h3);
                    ldsm4t(VLb + boff + (u32)ntp * 32u + kb, l0, l1, l2, l3);
#pragma unroll
                    for (int mt = 0; mt < 2; mt++) {
                        mma16816(kva[mt][2*ntp],   ah[mt][0], ah[mt][1], ah[mt][2], ah[mt][3], h0, h1);
                        mma16816(kva[mt][2*ntp],   ah[mt][0], ah[mt][1], ah[mt][2], ah[mt][3], l0, l1);
                        mma16816(kva[mt][2*ntp],   al[mt][0], al[mt][1], al[mt][2], al[mt][3], h0, h1);
                        mma16816(kva[mt][2*ntp+1], ah[mt][0], ah[mt][1], ah[mt][2], ah[mt][3], h2, h3);
                        mma16816(kva[mt][2*ntp+1], ah[mt][0], ah[mt][1], ah[mt][2], ah[mt][3], l2, l3);
                        mma16816(kva[mt][2*ntp+1], al[mt][0], al[mt][1], al[mt][2], al[mt][3], h2, h3);
                    }
                }
                u32 o0, o1;
                ldsm2t(VHb + b2off + kb, o0, o1);
#pragma unroll
                for (int mt = 0; mt < 2; mt++) {
                    mma16816(kva[mt][8], ah[mt][0], ah[mt][1], ah[mt][2], ah[mt][3], o0, o1);
                    mma16816(kva[mt][8], al[mt][0], al[mt][1], al[mt][2], al[mt][3], o0, o1);
                }
            }
        }
        __syncthreads();
    }
    // epilogue: scatter KV^T and ksum (k-halves merge via atomics)
#pragma unroll
    for (int mt = 0; mt < 2; mt++) {
        const int f0 = F0 + wm * 32 + (lane >> 2) + mt * 16;
#pragma unroll
        for (int nt = 0; nt < 9; nt++) {
            const int d = nt * 8 + (lane & 3) * 2;
            if (nt < 8) {
                atomicAdd(g_kvT + ((size_t)b * DD + d)     * FF + f0,      kva[mt][nt][0]);
                atomicAdd(g_kvT + ((size_t)b * DD + d + 1) * FF + f0,      kva[mt][nt][1]);
                atomicAdd(g_kvT + ((size_t)b * DD + d)     * FF + f0 + 8,  kva[mt][nt][2]);
                atomicAdd(g_kvT + ((size_t)b * DD + d + 1) * FF + f0 + 8,  kva[mt][nt][3]);
            } else if ((lane & 3) == 0) {
                atomicAdd(g_ksum + b * FF + f0,     kva[mt][nt][0]);
                atomicAdd(g_ksum + b * FF + f0 + 8, kva[mt][nt][2]);
            }
        }
    }
}

// ---------------- out: phi_q @ KV^T / deno ------------------------------------
// No q-side row-max and no q-side nsq: any per-row scalar on phi_q cancels
// between numerator and denominator (clamp inert; fp32 range verified).
#define OU_WH 0u
#define OU_WL 36864u
#define OU_QH 73728u
#define OU_QL 92160u
#define OU_PH 110592u
#define OU_PL 129024u
#define OU_KVH 147456u
#define OU_KVL 181248u
#define OU_KS 215040u
#define OU_DE 216064u
#define OU_SMEM (OU_DE + 1024u)
__global__ void __launch_bounds__(256, 1)
out_kernel(const float* __restrict__ q, const float* __restrict__ w, float* __restrict__ out) {
    extern __shared__ __align__(16) char sm[];
    const u32 smb = smem_u32(sm);
    const int tid = threadIdx.x, wid = tid >> 5, lane = tid & 31;
    const int wm = wid & 3, wn = wid >> 2;
    const int b = blockIdx.x, s0 = blockIdx.y * 128;
    float* ksum_s = (float*)(sm + OU_KS);
    float* dn2    = (float*)(sm + OU_DE);   // [2][128]
    float* scr    = (float*)(sm + OU_PH);   // overlay: [128][66] f32 reduction scratch
    ksum_s[tid] = g_ksum[b * FF + tid];
    stage_row(smb + OU_WH, smb + OU_WL, (const float4*)(w + tid * DD), tid, 1.0f, 0, 0);
    if (tid < 128) {
        stage_row(smb + OU_QH, smb + OU_QL, (const float4*)(q + (size_t)(b * SS + s0 + tid) * DD),
                  tid, INV_SIGMA, 0, 0);
    } else {   // KV^T tile [d][f] hi/lo, pitch 528
        const int d = (tid - 128) >> 1, half = tid & 1;
        const float* src = g_kvT + (size_t)b * DD * FF + d * FF + half * 128;
        const u32 rb = (u32)d * 528u + (u32)half * 256u;
#pragma unroll 8
        for (int j = 0; j < 64; j++) {
            u32 hi, lo;
            split2(src[2*j], src[2*j+1], hi, lo);
            sts32(smb + OU_KVH + rb + 4u * j, hi);
            sts32(smb + OU_KVL + rb + 4u * j, lo);
        }
    }
    __syncthreads();

    const u32 qH = smb + OU_QH + (u32)(wm * 32) * 144u;
    const u32 qL = smb + OU_QL + (u32)(wm * 32) * 144u;
    float dp[4] = {0.f, 0.f, 0.f, 0.f};

    float oacc[2][8][4];
#pragma unroll
    for (int mt = 0; mt < 2; mt++)
#pragma unroll
        for (int nt = 0; nt < 8; nt++)
#pragma unroll
            for (int j = 0; j < 4; j++) oacc[mt][nt][j] = 0.0f;

    for (int ch = 0; ch < 4; ch++) {
        float acc[2][4][4];
#pragma unroll
        for (int mt = 0; mt < 2; mt++)
#pragma unroll
            for (int nt = 0; nt < 4; nt++)
#pragma unroll
                for (int j = 0; j < 4; j++) acc[mt][nt][j] = 0.0f;
        mma_hl2<4>(acc, qH, qL, smb + OU_WH + (u32)(ch * 64 + wn * 32) * 144u,
                   smb + OU_WL + (u32)(ch * 64 + wn * 32) * 144u, 4, 144u, 144u);
#pragma unroll
        for (int nt = 0; nt < 4; nt++) {
            const int fl = wn * 32 + nt * 8 + (lane & 3) * 2;
            const int fg = ch * 64 + fl;
            const float ks0 = ksum_s[fg], ks1 = ksum_s[fg + 1];
#pragma unroll
            for (int mt = 0; mt < 2; mt++) {
                const int rb = wm * 32 + (lane >> 2) + mt * 16;
                float p00 = __expf(acc[mt][nt][0]) * INV_SQRT_F;
                float p01 = __expf(acc[mt][nt][1]) * INV_SQRT_F;
                float p10 = __expf(acc[mt][nt][2]) * INV_SQRT_F;
                float p11 = __expf(acc[mt][nt][3]) * INV_SQRT_F;
                dp[2*mt]     += p00 * ks0 + p01 * ks1;
                dp[2*mt + 1] += p10 * ks0 + p11 * ks1;
                u32 hi, lo;
                split2(p00, p01, hi, lo);
                sts32(smb + OU_PH + (u32)rb * 144u + 2u * fl, hi);
                sts32(smb + OU_PL + (u32)rb * 144u + 2u * fl, lo);
                split2(p10, p11, hi, lo);
                sts32(smb + OU_PH + (u32)(rb + 8) * 144u + 2u * fl, hi);
                sts32(smb + OU_PL + (u32)(rb + 8) * 144u + 2u * fl, lo);
            }
        }
        __syncthreads();
        // gemm: warp (wm rows, wn 32-f k-half of this chunk)
        mma_hl2<8>(oacc, smb + OU_PH + (u32)(wm * 32) * 144u + (u32)(wn * 64),
                         smb + OU_PL + (u32)(wm * 32) * 144u + (u32)(wn * 64),
                         smb + OU_KVH + (u32)(ch * 128 + wn * 64),
                         smb + OU_KVL + (u32)(ch * 128 + wn * 64), 2, 144u, 528u);
        __syncthreads();
    }
    // deno partials
#pragma unroll
    for (int j = 0; j < 4; j++) {
        dp[j] += __shfl_xor_sync(~0u, dp[j], 1);
        dp[j] += __shfl_xor_sync(~0u, dp[j], 2);
    }
    if ((lane & 3) == 0)
#pragma unroll
        for (int j = 0; j < 4; j++)
            dn2[wn * 128 + wm * 32 + (lane >> 2) + j * 8] = dp[j];
    __syncthreads();
    // reduce wn k-halves: wn1 spills to scratch (overlays dead phi buffer)
    if (wn == 1) {
#pragma unroll
        for (int nt = 0; nt < 8; nt++) {
            const int d = nt * 8 + (lane & 3) * 2;
#pragma unroll
            for (int mt = 0; mt < 2; mt++) {
                const int rb = wm * 32 + (lane >> 2) + mt * 16;
                *(float2*)(scr + rb * 66 + d)       = make_float2(oacc[mt][nt][0], oacc[mt][nt][1]);
                *(float2*)(scr + (rb + 8) * 66 + d) = make_float2(oacc[mt][nt][2], oacc[mt][nt][3]);
            }
        }
    }
    __syncthreads();
    if (wn == 0) {
        float inv[4];
#pragma unroll
        for (int j = 0; j < 4; j++) {
            const int r = wm * 32 + (lane >> 2) + j * 8;
            inv[j] = 1.0f / fmaxf(dn2[r] + dn2[128 + r], 1e-4f);
        }
#pragma unroll
        for (int nt = 0; nt < 8; nt++) {
            const int d = nt * 8 + (lane & 3) * 2;
#pragma unroll
            for (int mt = 0; mt < 2; mt++) {
                const int rb = wm * 32 + (lane >> 2) + mt * 16;
                float2 s0v = *(const float2*)(scr + rb * 66 + d);
                float2 s1v = *(const float2*)(scr + (rb + 8) * 66 + d);
                *(float2*)(out + (size_t)(b * SS + s0 + rb) * DD + d) =
                    make_float2((oacc[mt][nt][0] + s0v.x) * inv[2*mt],
                                (oacc[mt][nt][1] + s0v.y) * inv[2*mt]);
                *(float2*)(out + (size_t)(b * SS + s0 + rb + 8) * DD + d) =
                    make_float2((oacc[mt][nt][2] + s1v.x) * inv[2*mt + 1],
                                (oacc[mt][nt][3] + s1v.y) * inv[2*mt + 1]);
            }
        }
    }
}

// ---------------- launch ------------------------------------------------------
extern "C" void kernel_launch(void* const* d_in, const int* in_sizes, int n_in,
                              void* d_out, int out_size) {
    const float* q = (const float*)d_in[0];
    const float* k = (const float*)d_in[1];
    const float* v = (const float*)d_in[2];
    const float* w = (const float*)d_in[3];
    float* out = (float*)d_out;
    cudaFuncSetAttribute(kv_kernel,  cudaFuncAttributeMaxDynamicSharedMemorySize, KV_SMEM);
    cudaFuncSetAttribute(out_kernel, cudaFuncAttributeMaxDynamicSharedMemorySize, OU_SMEM);
    init_kernel<<<(BB * DD * FF + 255) / 256, 256>>>();
    mean_kernel<<<dim3(BB, 4), 256>>>(k);
    kv_kernel<<<dim3(BB, 2, 8), 256, KV_SMEM>>>(k, v, w);
    out_kernel<<<dim3(BB, SS / 128), 256, OU_SMEM>>>(q, w, out);
}

// round 9
// speedup vs baseline: 1.2912x; 1.1346x over previous
#include <cuda_runtime.h>
#include <cuda_bf16.h>

typedef unsigned u32; typedef unsigned long long u64;
#define BB 64
#define SS 4096
#define DD 64
#define FF 256
#define INV_SIGMA 0.3535533905932738f
#define INV_SQRT_F 0.0625f

__device__ float g_mean[BB * DD];
__device__ float g_kvT [BB * DD * FF];   // [b][d][f]
__device__ float g_ksum[BB * FF];

// ---------------- helpers ----------------------------------------------------
__device__ __forceinline__ u32 smem_u32(const void* p) {
    u32 a; asm("{ .reg .u64 t; cvta.to.shared.u64 t, %1; cvt.u32.u64 %0, t; }" : "=r"(a) : "l"(p));
    return a;
}
__device__ __forceinline__ void sts32(u32 a, u32 v) {
    asm volatile("st.shared.b32 [%0], %1;" :: "r"(a), "r"(v) : "memory");
}
__device__ __forceinline__ void split2(float a, float b, u32& hi, u32& lo) {
    u32 h; asm("cvt.rn.bf16x2.f32 %0,%1,%2;" : "=r"(h) : "f"(b), "f"(a));
    float ah = __uint_as_float(h << 16), bh = __uint_as_float(h & 0xffff0000u);
    float ar = a - ah, br = b - bh;
    asm("cvt.rn.bf16x2.f32 %0,%1,%2;" : "=r"(lo) : "f"(br), "f"(ar));
    hi = h;
}
__device__ __forceinline__ void ldsm4(u32 a, u32& r0, u32& r1, u32& r2, u32& r3) {
    asm volatile("ldmatrix.sync.aligned.m8n8.x4.shared.b16 {%0,%1,%2,%3}, [%4];"
                 : "=r"(r0), "=r"(r1), "=r"(r2), "=r"(r3) : "r"(a));
}
__device__ __forceinline__ void ldsm4t(u32 a, u32& r0, u32& r1, u32& r2, u32& r3) {
    asm volatile("ldmatrix.sync.aligned.m8n8.x4.trans.shared.b16 {%0,%1,%2,%3}, [%4];"
                 : "=r"(r0), "=r"(r1), "=r"(r2), "=r"(r3) : "r"(a));
}
__device__ __forceinline__ void ldsm2t(u32 a, u32& r0, u32& r1) {
    asm volatile("ldmatrix.sync.aligned.m8n8.x2.trans.shared.b16 {%0,%1}, [%2];"
                 : "=r"(r0), "=r"(r1) : "r"(a));
}
__device__ __forceinline__ void mma16816(float* c, u32 a0, u32 a1, u32 a2, u32 a3, u32 b0, u32 b1) {
    asm volatile("mma.sync.aligned.m16n8k16.row.col.f32.bf16.bf16.f32 "
                 "{%0,%1,%2,%3},{%4,%5,%6,%7},{%8,%9},{%0,%1,%2,%3};"
                 : "+f"(c[0]), "+f"(c[1]), "+f"(c[2]), "+f"(c[3])
                 : "r"(a0), "r"(a1), "r"(a2), "r"(a3), "r"(b0), "r"(b1));
}

// stage one 64-float row as bf16 hi(/lo) into pitch-144B tile at row r
__device__ __forceinline__ void stage_row(u32 hB, u32 lB, const float4* src, int r, float scale,
                                          const float* cen, float* nsq_out) {
    u32 rb = (u32)r * 144u;
    float nsq = 0.0f;
#pragma unroll
    for (int i = 0; i < 16; i++) {
        float4 x = src[i];
        float c0 = x.x * scale, c1 = x.y * scale, c2 = x.z * scale, c3 = x.w * scale;
        if (cen) { c0 -= cen[4*i]; c1 -= cen[4*i+1]; c2 -= cen[4*i+2]; c3 -= cen[4*i+3]; }
        if (nsq_out) nsq += c0*c0 + c1*c1 + c2*c2 + c3*c3;
        u32 h0, l0, h1, l1;
        split2(c0, c1, h0, l0); split2(c2, c3, h1, l1);
        sts32(hB + rb + i * 8u, h0); sts32(hB + rb + i * 8u + 4u, h1);
        if (lB) { sts32(lB + rb + i * 8u, l0); sts32(lB + rb + i * 8u + 4u, l1); }
    }
    if (nsq_out) *nsq_out = 0.5f * nsq;
}

// 2-mtile fused hi/lo GEMM (HH + HL + LH)
template<int NT>
__device__ __forceinline__ void mma_hl2(float (&acc)[2][NT][4], u32 aH, u32 aL,
                                        u32 bH, u32 bL, int nk, u32 ap, u32 bp) {
    const int lane = threadIdx.x & 31;
    const u32 aoff = (u32)(lane & 15) * ap + (u32)(lane >> 4) * 16u;
    const u32 boff = (u32)(lane & 15) * bp + (u32)(lane >> 4) * 16u;
    for (int kk = 0; kk < nk; kk++) {
        u32 ah[2][4], al[2][4];
#pragma unroll
        for (int mt = 0; mt < 2; mt++) {
            ldsm4(aH + aoff + (u32)mt * 16u * ap + (u32)kk * 32u,
                  ah[mt][0], ah[mt][1], ah[mt][2], ah[mt][3]);
            ldsm4(aL + aoff + (u32)mt * 16u * ap + (u32)kk * 32u,
                  al[mt][0], al[mt][1], al[mt][2], al[mt][3]);
        }
#pragma unroll
        for (int ntp = 0; ntp < NT / 2; ntp++) {
            u32 h0, h1, h2, h3, l0, l1, l2, l3;
            ldsm4(bH + boff + (u32)ntp * 16u * bp + (u32)kk * 32u, h0, h1, h2, h3);
            ldsm4(bL + boff + (u32)ntp * 16u * bp + (u32)kk * 32u, l0, l1, l2, l3);
#pragma unroll
            for (int mt = 0; mt < 2; mt++) {
                mma16816(acc[mt][2*ntp],   ah[mt][0], ah[mt][1], ah[mt][2], ah[mt][3], h0, h2);
                mma16816(acc[mt][2*ntp],   ah[mt][0], ah[mt][1], ah[mt][2], ah[mt][3], l0, l2);
                mma16816(acc[mt][2*ntp],   al[mt][0], al[mt][1], al[mt][2], al[mt][3], h0, h2);
                mma16816(acc[mt][2*ntp+1], ah[mt][0], ah[mt][1], ah[mt][2], ah[mt][3], h1, h3);
                mma16816(acc[mt][2*ntp+1], ah[mt][0], ah[mt][1], ah[mt][2], ah[mt][3], l1, l3);
                mma16816(acc[mt][2*ntp+1], al[mt][0], al[mt][1], al[mt][2], al[mt][3], h1, h3);
            }
        }
    }
}

// ---------------- init + mean ------------------------------------------------
__global__ void init_kernel() {
    int i = blockIdx.x * 256 + threadIdx.x;
    if (i < BB * DD * FF) g_kvT[i] = 0.0f;
    if (i < BB * FF)      g_ksum[i] = 0.0f;
    if (i < BB * DD)      g_mean[i] = 0.0f;
}
__global__ void mean_kernel(const float* __restrict__ k) {
    const int b = blockIdx.x, p = blockIdx.y;
    const int d = threadIdx.x & 63, sub = threadIdx.x >> 6;
    const float* kp = k + (size_t)(b * SS + p * 1024) * DD;
    float s = 0.0f;
    for (int r = sub; r < 1024; r += 4) s += kp[r * DD + d];
    __shared__ float sm[4][DD];
    sm[sub][d] = s; __syncthreads();
    if (threadIdx.x < DD)
        atomicAdd(&g_mean[b * DD + threadIdx.x],
                  sm[0][threadIdx.x] + sm[1][threadIdx.x] + sm[2][threadIdx.x] + sm[3][threadIdx.x]);
}

// ---------------- kv: KV[d,f] (+ksum) = (phi_k^T @ [V | 1])^T -----------------
#define KV_WH 0u
#define KV_WL 18432u
#define KV_KH 36864u
#define KV_KL 55296u
#define KV_PH 73728u
#define KV_PL 108544u
#define KV_VH 143360u
#define KV_VL 161792u
#define KV_ME 180224u
#define KV_NS 180480u
#define KV_SMEM (KV_NS + 512u)
__global__ void __launch_bounds__(256, 1)
kv_kernel(const float* __restrict__ k, const float* __restrict__ v, const float* __restrict__ w) {
    extern __shared__ __align__(16) char sm[];
    const u32 smb = smem_u32(sm);
    const int tid = threadIdx.x, wid = tid >> 5, lane = tid & 31;
    const int wm = wid & 3, wn = wid >> 2;
    const int b = blockIdx.x, F0 = blockIdx.y * 128;
    float* meanc = (float*)(sm + KV_ME);
    float* nsqs  = (float*)(sm + KV_NS);
    if (tid < DD) meanc[tid] = g_mean[b * DD + tid] * (INV_SIGMA / (float)SS);
    if (tid < 128)
        stage_row(smb + KV_WH, smb + KV_WL, (const float4*)(w + (F0 + tid) * DD), tid, 1.0f, 0, 0);
    __syncthreads();

    float kva[2][9][4];
#pragma unroll
    for (int mt = 0; mt < 2; mt++)
#pragma unroll
        for (int nt = 0; nt < 9; nt++)
#pragma unroll
            for (int j = 0; j < 4; j++) kva[mt][nt][j] = 0.0f;

    for (int t = 0; t < 8; t++) {
        const int s0 = (blockIdx.z * 8 + t) * 128;
        if (tid < 128) {       // stage K rows (hi/lo, pitch 144)
            float nsq;
            stage_row(smb + KV_KH, smb + KV_KL,
                      (const float4*)(k + (size_t)(b * SS + s0 + tid) * DD), tid, INV_SIGMA, meanc, &nsq);
            nsqs[tid] = nsq;
        } else {               // stage V row [s][72] + ones cols (coalesced)
            const int sv = tid - 128;
            const float4* vr = (const float4*)(v + (size_t)(b * SS + s0 + sv) * DD);
            const u32 rb = (u32)sv * 144u;
#pragma unroll
            for (int i = 0; i < 16; i++) {
                float4 x = vr[i];
                u32 h0, l0, h1, l1;
                split2(x.x, x.y, h0, l0); split2(x.z, x.w, h1, l1);
                sts32(smb + KV_VH + rb + i * 8u,      h0);
                sts32(smb + KV_VH + rb + i * 8u + 4u, h1);
                sts32(smb + KV_VL + rb + i * 8u,      l0);
                sts32(smb + KV_VL + rb + i * 8u + 4u, l1);
            }
#pragma unroll
            for (int j = 0; j < 4; j++) {
                sts32(smb + KV_VH + rb + 128u + 4u * j, 0x3F803F80u);
                sts32(smb + KV_VL + rb + 128u + 4u * j, 0u);
            }
        }
        __syncthreads();
        // proj: warp (wm: 32 s-rows, wn: 64 f); fused 3-pass hi/lo
        {
            float acc[2][8][4];
#pragma unroll
            for (int mt = 0; mt < 2; mt++)
#pragma unroll
                for (int nt = 0; nt < 8; nt++)
#pragma unroll
                    for (int j = 0; j < 4; j++) acc[mt][nt][j] = 0.0f;
            mma_hl2<8>(acc, smb + KV_KH + (u32)(wm * 32) * 144u,
                            smb + KV_KL + (u32)(wm * 32) * 144u,
                            smb + KV_WH + (u32)(wn * 64) * 144u,
                            smb + KV_WL + (u32)(wn * 64) * 144u, 4, 144u, 144u);
            // exp + store phi natural [s][f] pitch 272
            float n[4];
#pragma unroll
            for (int j = 0; j < 4; j++)
                n[j] = nsqs[wm * 32 + (lane >> 2) + j * 8];
#pragma unroll
            for (int nt = 0; nt < 8; nt++) {
                const int f = wn * 64 + nt * 8 + (lane & 3) * 2;
#pragma unroll
                for (int mt = 0; mt < 2; mt++) {
                    const int rb = wm * 32 + (lane >> 2) + mt * 16;
                    float p00 = __expf(acc[mt][nt][0] - n[2*mt])     * INV_SQRT_F;
                    float p01 = __expf(acc[mt][nt][1] - n[2*mt])     * INV_SQRT_F;
                    float p10 = __expf(acc[mt][nt][2] - n[2*mt + 1]) * INV_SQRT_F;
                    float p11 = __expf(acc[mt][nt][3] - n[2*mt + 1]) * INV_SQRT_F;
                    u32 hi, lo;
                    split2(p00, p01, hi, lo);
                    sts32(smb + KV_PH + (u32)rb * 272u + 2u * f, hi);
                    sts32(smb + KV_PL + (u32)rb * 272u + 2u * f, lo);
                    split2(p10, p11, hi, lo);
                    sts32(smb + KV_PH + (u32)(rb + 8) * 272u + 2u * f, hi);
                    sts32(smb + KV_PL + (u32)(rb + 8) * 272u + 2u * f, lo);
                }
            }
        }
        __syncthreads();
        // kv gemm: warp (wm: 32 f-rows, wn: 64-s k-half); trans loads
        {
            const u32 aoff = ((u32)(lane & 7) + (u32)((lane >> 4) & 1) * 8u) * 272u +
                             (u32)((lane >> 3) & 1) * 16u + (u32)(wm * 64) +
                             (u32)(wn * 64) * 272u;
            const u32 boff = ((u32)(lane & 7) + (u32)((lane >> 3) & 1) * 8u) * 144u +
                             (u32)((lane >> 4) & 1) * 16u + (u32)(wn * 64) * 144u;
            const u32 b2off = ((u32)(lane & 7) + (u32)((lane >> 3) & 1) * 8u) * 144u + 128u +
                              (u32)(wn * 64) * 144u;
            const u32 PHb = smb + KV_PH, PLb = smb + KV_PL;
            const u32 VHb = smb + KV_VH, VLb = smb + KV_VL;
            for (int kk = 0; kk < 4; kk++) {
                const u32 ka = (u32)kk * 16u * 272u, kb = (u32)kk * 16u * 144u;
                u32 ah[2][4], al[2][4];
#pragma unroll
                for (int mt = 0; mt < 2; mt++) {
                    ldsm4t(PHb + aoff + (u32)(mt * 32) + ka, ah[mt][0], ah[mt][1], ah[mt][2], ah[mt][3]);
                    ldsm4t(PLb + aoff + (u32)(mt * 32) + ka, al[mt][0], al[mt][1], al[mt][2], al[mt][3]);
                }
#pragma unroll
                for (int ntp = 0; ntp < 4; ntp++) {
                    u32 h0, h1, h2, h3, l0, l1, l2, l3;
                    ldsm4t(VHb + boff + (u32)ntp * 32u + kb, h0, h1, h2, h3);
                    ldsm4t(VLb + boff + (u32)ntp * 32u + kb, l0, l1, l2, l3);
#pragma unroll
                    for (int mt = 0; mt < 2; mt++) {
                        mma16816(kva[mt][2*ntp],   ah[mt][0], ah[mt][1], ah[mt][2], ah[mt][3], h0, h1);
                        mma16816(kva[mt][2*ntp],   ah[mt][0], ah[mt][1], ah[mt][2], ah[mt][3], l0, l1);
                        mma16816(kva[mt][2*ntp],   al[mt][0], al[mt][1], al[mt][2], al[mt][3], h0, h1);
                        mma16816(kva[mt][2*ntp+1], ah[mt][0], ah[mt][1], ah[mt][2], ah[mt][3], h2, h3);
                        mma16816(kva[mt][2*ntp+1], ah[mt][0], ah[mt][1], ah[mt][2], ah[mt][3], l2, l3);
                        mma16816(kva[mt][2*ntp+1], al[mt][0], al[mt][1], al[mt][2], al[mt][3], h2, h3);
                    }
                }
                u32 o0, o1;
                ldsm2t(VHb + b2off + kb, o0, o1);
#pragma unroll
                for (int mt = 0; mt < 2; mt++) {
                    mma16816(kva[mt][8], ah[mt][0], ah[mt][1], ah[mt][2], ah[mt][3], o0, o1);
                    mma16816(kva[mt][8], al[mt][0], al[mt][1], al[mt][2], al[mt][3], o0, o1);
                }
            }
        }
        __syncthreads();
    }
    // epilogue: scatter KV^T and ksum (k-halves merge via atomics)
#pragma unroll
    for (int mt = 0; mt < 2; mt++) {
        const int f0 = F0 + wm * 32 + (lane >> 2) + mt * 16;
#pragma unroll
        for (int nt = 0; nt < 9; nt++) {
            const int d = nt * 8 + (lane & 3) * 2;
            if (nt < 8) {
                atomicAdd(g_kvT + ((size_t)b * DD + d)     * FF + f0,      kva[mt][nt][0]);
                atomicAdd(g_kvT + ((size_t)b * DD + d + 1) * FF + f0,      kva[mt][nt][1]);
                atomicAdd(g_kvT + ((size_t)b * DD + d)     * FF + f0 + 8,  kva[mt][nt][2]);
                atomicAdd(g_kvT + ((size_t)b * DD + d + 1) * FF + f0 + 8,  kva[mt][nt][3]);
            } else if ((lane & 3) == 0) {
                atomicAdd(g_ksum + b * FF + f0,     kva[mt][nt][0]);
                atomicAdd(g_ksum + b * FF + f0 + 8, kva[mt][nt][2]);
            }
        }
    }
}

// ---------------- out: phi_q @ KV^T / deno ------------------------------------
// Multi-tile CTA: W, KV, ksum staged once, then 4 s-tiles of 128 rows.
#define OU_WH 0u
#define OU_WL 36864u
#define OU_QH 73728u
#define OU_QL 92160u
#define OU_PH 110592u
#define OU_PL 129024u
#define OU_KVH 147456u
#define OU_KVL 181248u
#define OU_KS 215040u
#define OU_DE 216064u
#define OU_SMEM (OU_DE + 1024u)
__global__ void __launch_bounds__(256, 1)
out_kernel(const float* __restrict__ q, const float* __restrict__ w, float* __restrict__ out) {
    extern __shared__ __align__(16) char sm[];
    const u32 smb = smem_u32(sm);
    const int tid = threadIdx.x, wid = tid >> 5, lane = tid & 31;
    const int wm = wid & 3, wn = wid >> 2;
    const int b = blockIdx.x;
    float* ksum_s = (float*)(sm + OU_KS);
    float* dn2    = (float*)(sm + OU_DE);   // [2][128]
    float* scr    = (float*)(sm + OU_PH);   // overlay: [128][66] f32 reduction scratch
    ksum_s[tid] = g_ksum[b * FF + tid];
    stage_row(smb + OU_WH, smb + OU_WL, (const float4*)(w + tid * DD), tid, 1.0f, 0, 0);
    if (tid >= 128) {   // KV^T tile [d][f] hi/lo, pitch 528
        const int d = (tid - 128) >> 1, half = tid & 1;
        const float* src = g_kvT + (size_t)b * DD * FF + d * FF + half * 128;
        const u32 rb = (u32)d * 528u + (u32)half * 256u;
#pragma unroll 8
        for (int j = 0; j < 64; j++) {
            u32 hi, lo;
            split2(src[2*j], src[2*j+1], hi, lo);
            sts32(smb + OU_KVH + rb + 4u * j, hi);
            sts32(smb + OU_KVL + rb + 4u * j, lo);
        }
    }

    const u32 qH = smb + OU_QH + (u32)(wm * 32) * 144u;
    const u32 qL = smb + OU_QL + (u32)(wm * 32) * 144u;

    for (int tt = 0; tt < 4; tt++) {
        const int s0 = (blockIdx.y * 4 + tt) * 128;
        __syncthreads();   // prev tile fully consumed (or staging pending on tt=0)
        if (tid < 128)
            stage_row(smb + OU_QH, smb + OU_QL,
                      (const float4*)(q + (size_t)(b * SS + s0 + tid) * DD), tid, INV_SIGMA, 0, 0);
        __syncthreads();

        float dp[4] = {0.f, 0.f, 0.f, 0.f};
        float oacc[2][8][4];
#pragma unroll
        for (int mt = 0; mt < 2; mt++)
#pragma unroll
            for (int nt = 0; nt < 8; nt++)
#pragma unroll
                for (int j = 0; j < 4; j++) oacc[mt][nt][j] = 0.0f;

        for (int ch = 0; ch < 4; ch++) {
            float acc[2][4][4];
#pragma unroll
            for (int mt = 0; mt < 2; mt++)
#pragma unroll
                for (int nt = 0; nt < 4; nt++)
#pragma unroll
                    for (int j = 0; j < 4; j++) acc[mt][nt][j] = 0.0f;
            mma_hl2<4>(acc, qH, qL, smb + OU_WH + (u32)(ch * 64 + wn * 32) * 144u,
                       smb + OU_WL + (u32)(ch * 64 + wn * 32) * 144u, 4, 144u, 144u);
#pragma unroll
            for (int nt = 0; nt < 4; nt++) {
                const int fl = wn * 32 + nt * 8 + (lane & 3) * 2;
                const int fg = ch * 64 + fl;
                const float ks0 = ksum_s[fg], ks1 = ksum_s[fg + 1];
#pragma unroll
                for (int mt = 0; mt < 2; mt++) {
                    const int rb = wm * 32 + (lane >> 2) + mt * 16;
                    float p00 = __expf(acc[mt][nt][0]) * INV_SQRT_F;
                    float p01 = __expf(acc[mt][nt][1]) * INV_SQRT_F;
                    float p10 = __expf(acc[mt][nt][2]) * INV_SQRT_F;
                    float p11 = __expf(acc[mt][nt][3]) * INV_SQRT_F;
                    dp[2*mt]     += p00 * ks0 + p01 * ks1;
                    dp[2*mt + 1] += p10 * ks0 + p11 * ks1;
                    u32 hi, lo;
                    split2(p00, p01, hi, lo);
                    sts32(smb + OU_PH + (u32)rb * 144u + 2u * fl, hi);
                    sts32(smb + OU_PL + (u32)rb * 144u + 2u * fl, lo);
                    split2(p10, p11, hi, lo);
                    sts32(smb + OU_PH + (u32)(rb + 8) * 144u + 2u * fl, hi);
                    sts32(smb + OU_PL + (u32)(rb + 8) * 144u + 2u * fl, lo);
                }
            }
            __syncthreads();
            // gemm: warp (wm rows, wn 32-f k-half of this chunk)
            mma_hl2<8>(oacc, smb + OU_PH + (u32)(wm * 32) * 144u + (u32)(wn * 64),
                             smb + OU_PL + (u32)(wm * 32) * 144u + (u32)(wn * 64),
                             smb + OU_KVH + (u32)(ch * 128 + wn * 64),
                             smb + OU_KVL + (u32)(ch * 128 + wn * 64), 2, 144u, 528u);
            __syncthreads();
        }
        // deno partials
#pragma unroll
        for (int j = 0; j < 4; j++) {
            dp[j] += __shfl_xor_sync(~0u, dp[j], 1);
            dp[j] += __shfl_xor_sync(~0u, dp[j], 2);
        }
        if ((lane & 3) == 0)
#pragma unroll
            for (int j = 0; j < 4; j++)
                dn2[wn * 128 + wm * 32 + (lane >> 2) + j * 8] = dp[j];
        // reduce wn k-halves: wn1 spills to scratch (overlays dead phi buffer)
        if (wn == 1) {
#pragma unroll
            for (int nt = 0; nt < 8; nt++) {
                const int d = nt * 8 + (lane & 3) * 2;
#pragma unroll
                for (int mt = 0; mt < 2; mt++) {
                    const int rb = wm * 32 + (lane >> 2) + mt * 16;
                    *(float2*)(scr + rb * 66 + d)       = make_float2(oacc[mt][nt][0], oacc[mt][nt][1]);
                    *(float2*)(scr + (rb + 8) * 66 + d) = make_float2(oacc[mt][nt][2], oacc[mt][nt][3]);
                }
            }
        }
        __syncthreads();
        if (wn == 0) {
            float inv[4];
#pragma unroll
            for (int j = 0; j < 4; j++) {
                const int r = wm * 32 + (lane >> 2) + j * 8;
                inv[j] = 1.0f / fmaxf(dn2[r] + dn2[128 + r], 1e-4f);
            }
#pragma unroll
            for (int nt = 0; nt < 8; nt++) {
                const int d = nt * 8 + (lane & 3) * 2;
#pragma unroll
                for (int mt = 0; mt < 2; mt++) {
                    const int rb = wm * 32 + (lane >> 2) + mt * 16;
                    float2 s0v = *(const float2*)(scr + rb * 66 + d);
                    float2 s1v = *(const float2*)(scr + (rb + 8) * 66 + d);
                    *(float2*)(out + (size_t)(b * SS + s0 + rb) * DD + d) =
                        make_float2((oacc[mt][nt][0] + s0v.x) * inv[2*mt],
                                    (oacc[mt][nt][1] + s0v.y) * inv[2*mt]);
                    *(float2*)(out + (size_t)(b * SS + s0 + rb + 8) * DD + d) =
                        make_float2((oacc[mt][nt][2] + s1v.x) * inv[2*mt + 1],
                                    (oacc[mt][nt][3] + s1v.y) * inv[2*mt + 1]);
                }
            }
        }
    }
}

// ---------------- launch ------------------------------------------------------
extern "C" void kernel_launch(void* const* d_in, const int* in_sizes, int n_in,
                              void* d_out, int out_size) {
    const float* q = (const float*)d_in[0];
    const float* k = (const float*)d_in[1];
    const float* v = (const float*)d_in[2];
    const float* w = (const float*)d_in[3];
    float* out = (float*)d_out;
    cudaFuncSetAttribute(kv_kernel,  cudaFuncAttributeMaxDynamicSharedMemorySize, KV_SMEM);
    cudaFuncSetAttribute(out_kernel, cudaFuncAttributeMaxDynamicSharedMemorySize, OU_SMEM);
    init_kernel<<<(BB * DD * FF + 255) / 256, 256>>>();
    mean_kernel<<<dim3(BB, 4), 256>>>(k);
    kv_kernel<<<dim3(BB, 2, 4), 256, KV_SMEM>>>(k, v, w);
    out_kernel<<<dim3(BB, 8), 256, OU_SMEM>>>(q, w, out);
}

// round 10
// speedup vs baseline: 1.3393x; 1.0373x over previous
#include <cuda_runtime.h>
#include <cuda_bf16.h>

typedef unsigned u32; typedef unsigned long long u64;
#define BB 64
#define SS 4096
#define DD 64
#define FF 256
#define INV_SIGMA 0.3535533905932738f
#define INV_SQRT_F 0.0625f

__device__ float g_mean[BB * DD];
__device__ float g_kvT [BB * DD * FF];   // [b][d][f]
__device__ float g_ksum[BB * FF];

// ---------------- helpers ----------------------------------------------------
__device__ __forceinline__ u32 smem_u32(const void* p) {
    u32 a; asm("{ .reg .u64 t; cvta.to.shared.u64 t, %1; cvt.u32.u64 %0, t; }" : "=r"(a) : "l"(p));
    return a;
}
__device__ __forceinline__ void sts32(u32 a, u32 v) {
    asm volatile("st.shared.b32 [%0], %1;" :: "r"(a), "r"(v) : "memory");
}
__device__ __forceinline__ void split2(float a, float b, u32& hi, u32& lo) {
    u32 h; asm("cvt.rn.bf16x2.f32 %0,%1,%2;" : "=r"(h) : "f"(b), "f"(a));
    float ah = __uint_as_float(h << 16), bh = __uint_as_float(h & 0xffff0000u);
    float ar = a - ah, br = b - bh;
    asm("cvt.rn.bf16x2.f32 %0,%1,%2;" : "=r"(lo) : "f"(br), "f"(ar));
    hi = h;
}
__device__ __forceinline__ void ldsm4(u32 a, u32& r0, u32& r1, u32& r2, u32& r3) {
    asm volatile("ldmatrix.sync.aligned.m8n8.x4.shared.b16 {%0,%1,%2,%3}, [%4];"
                 : "=r"(r0), "=r"(r1), "=r"(r2), "=r"(r3) : "r"(a));
}
__device__ __forceinline__ void ldsm4t(u32 a, u32& r0, u32& r1, u32& r2, u32& r3) {
    asm volatile("ldmatrix.sync.aligned.m8n8.x4.trans.shared.b16 {%0,%1,%2,%3}, [%4];"
                 : "=r"(r0), "=r"(r1), "=r"(r2), "=r"(r3) : "r"(a));
}
__device__ __forceinline__ void ldsm2t(u32 a, u32& r0, u32& r1) {
    asm volatile("ldmatrix.sync.aligned.m8n8.x2.trans.shared.b16 {%0,%1}, [%2];"
                 : "=r"(r0), "=r"(r1) : "r"(a));
}
__device__ __forceinline__ void mma16816(float* c, u32 a0, u32 a1, u32 a2, u32 a3, u32 b0, u32 b1) {
    asm volatile("mma.sync.aligned.m16n8k16.row.col.f32.bf16.bf16.f32 "
                 "{%0,%1,%2,%3},{%4,%5,%6,%7},{%8,%9},{%0,%1,%2,%3};"
                 : "+f"(c[0]), "+f"(c[1]), "+f"(c[2]), "+f"(c[3])
                 : "r"(a0), "r"(a1), "r"(a2), "r"(a3), "r"(b0), "r"(b1));
}

// stage one 64-float row as bf16 hi(/lo) into pitch-144B tile at row r
__device__ __forceinline__ void stage_row(u32 hB, u32 lB, const float4* src, int r, float scale,
                                          const float* cen, float* nsq_out) {
    u32 rb = (u32)r * 144u;
    float nsq = 0.0f;
#pragma unroll
    for (int i = 0; i < 16; i++) {
        float4 x = src[i];
        float c0 = x.x * scale, c1 = x.y * scale, c2 = x.z * scale, c3 = x.w * scale;
        if (cen) { c0 -= cen[4*i]; c1 -= cen[4*i+1]; c2 -= cen[4*i+2]; c3 -= cen[4*i+3]; }
        if (nsq_out) nsq += c0*c0 + c1*c1 + c2*c2 + c3*c3;
        u32 h0, l0, h1, l1;
        split2(c0, c1, h0, l0); split2(c2, c3, h1, l1);
        sts32(hB + rb + i * 8u, h0); sts32(hB + rb + i * 8u + 4u, h1);
        if (lB) { sts32(lB + rb + i * 8u, l0); sts32(lB + rb + i * 8u + 4u, l1); }
    }
    if (nsq_out) *nsq_out = 0.5f * nsq;
}

// 2-mtile fused hi/lo GEMM (HH + HL + LH)
template<int NT>
__device__ __forceinline__ void mma_hl2(float (&acc)[2][NT][4], u32 aH, u32 aL,
                                        u32 bH, u32 bL, int nk, u32 ap, u32 bp) {
    const int lane = threadIdx.x & 31;
    const u32 aoff = (u32)(lane & 15) * ap + (u32)(lane >> 4) * 16u;
    const u32 boff = (u32)(lane & 15) * bp + (u32)(lane >> 4) * 16u;
    for (int kk = 0; kk < nk; kk++) {
        u32 ah[2][4], al[2][4];
#pragma unroll
        for (int mt = 0; mt < 2; mt++) {
            ldsm4(aH + aoff + (u32)mt * 16u * ap + (u32)kk * 32u,
                  ah[mt][0], ah[mt][1], ah[mt][2], ah[mt][3]);
            ldsm4(aL + aoff + (u32)mt * 16u * ap + (u32)kk * 32u,
                  al[mt][0], al[mt][1], al[mt][2], al[mt][3]);
        }
#pragma unroll
        for (int ntp = 0; ntp < NT / 2; ntp++) {
            u32 h0, h1, h2, h3, l0, l1, l2, l3;
            ldsm4(bH + boff + (u32)ntp * 16u * bp + (u32)kk * 32u, h0, h1, h2, h3);
            ldsm4(bL + boff + (u32)ntp * 16u * bp + (u32)kk * 32u, l0, l1, l2, l3);
#pragma unroll
            for (int mt = 0; mt < 2; mt++) {
                mma16816(acc[mt][2*ntp],   ah[mt][0], ah[mt][1], ah[mt][2], ah[mt][3], h0, h2);
                mma16816(acc[mt][2*ntp],   ah[mt][0], ah[mt][1], ah[mt][2], ah[mt][3], l0, l2);
                mma16816(acc[mt][2*ntp],   al[mt][0], al[mt][1], al[mt][2], al[mt][3], h0, h2);
                mma16816(acc[mt][2*ntp+1], ah[mt][0], ah[mt][1], ah[mt][2], ah[mt][3], h1, h3);
                mma16816(acc[mt][2*ntp+1], ah[mt][0], ah[mt][1], ah[mt][2], ah[mt][3], l1, l3);
                mma16816(acc[mt][2*ntp+1], al[mt][0], al[mt][1], al[mt][2], al[mt][3], h1, h3);
            }
        }
    }
}

// ---------------- init + mean ------------------------------------------------
__global__ void init_kernel() {
    int i = blockIdx.x * 256 + threadIdx.x;
    if (i < BB * DD * FF) g_kvT[i] = 0.0f;
    if (i < BB * FF)      g_ksum[i] = 0.0f;
    if (i < BB * DD)      g_mean[i] = 0.0f;
}
__global__ void mean_kernel(const float* __restrict__ k) {
    const int b = blockIdx.x, p = blockIdx.y;
    const int d = threadIdx.x & 63, sub = threadIdx.x >> 6;
    const float* kp = k + (size_t)(b * SS + p * 1024) * DD;
    float s = 0.0f;
    for (int r = sub; r < 1024; r += 4) s += kp[r * DD + d];
    __shared__ float sm[4][DD];
    sm[sub][d] = s; __syncthreads();
    if (threadIdx.x < DD)
        atomicAdd(&g_mean[b * DD + threadIdx.x],
                  sm[0][threadIdx.x] + sm[1][threadIdx.x] + sm[2][threadIdx.x] + sm[3][threadIdx.x]);
}

// ---------------- kv: KV[d,f] (+ksum) = (phi_k^T @ [V | 1])^T -----------------
#define KV_WH 0u
#define KV_WL 18432u
#define KV_KH 36864u
#define KV_KL 55296u
#define KV_PH 73728u
#define KV_PL 108544u
#define KV_VH 143360u
#define KV_VL 161792u
#define KV_ME 180224u
#define KV_NS 180480u
#define KV_SMEM (KV_NS + 512u)
__global__ void __launch_bounds__(256, 1)
kv_kernel(const float* __restrict__ k, const float* __restrict__ v, const float* __restrict__ w) {
    extern __shared__ __align__(16) char sm[];
    const u32 smb = smem_u32(sm);
    const int tid = threadIdx.x, wid = tid >> 5, lane = tid & 31;
    const int wm = wid & 3, wn = wid >> 2;
    const int b = blockIdx.x, F0 = blockIdx.y * 128;
    float* meanc = (float*)(sm + KV_ME);
    float* nsqs  = (float*)(sm + KV_NS);
    if (tid < DD) meanc[tid] = g_mean[b * DD + tid] * (INV_SIGMA / (float)SS);
    if (tid < 128)
        stage_row(smb + KV_WH, smb + KV_WL, (const float4*)(w + (F0 + tid) * DD), tid, 1.0f, 0, 0);
    __syncthreads();

    float kva[2][9][4];
#pragma unroll
    for (int mt = 0; mt < 2; mt++)
#pragma unroll
        for (int nt = 0; nt < 9; nt++)
#pragma unroll
            for (int j = 0; j < 4; j++) kva[mt][nt][j] = 0.0f;

    for (int t = 0; t < 8; t++) {
        const int s0 = (blockIdx.z * 8 + t) * 128;
        if (tid < 128) {       // stage K rows (hi/lo, pitch 144)
            float nsq;
            stage_row(smb + KV_KH, smb + KV_KL,
                      (const float4*)(k + (size_t)(b * SS + s0 + tid) * DD), tid, INV_SIGMA, meanc, &nsq);
            nsqs[tid] = nsq;
        } else {               // stage V row [s][72] + ones cols (coalesced)
            const int sv = tid - 128;
            const float4* vr = (const float4*)(v + (size_t)(b * SS + s0 + sv) * DD);
            const u32 rb = (u32)sv * 144u;
#pragma unroll
            for (int i = 0; i < 16; i++) {
                float4 x = vr[i];
                u32 h0, l0, h1, l1;
                split2(x.x, x.y, h0, l0); split2(x.z, x.w, h1, l1);
                sts32(smb + KV_VH + rb + i * 8u,      h0);
                sts32(smb + KV_VH + rb + i * 8u + 4u, h1);
                sts32(smb + KV_VL + rb + i * 8u,      l0);
                sts32(smb + KV_VL + rb + i * 8u + 4u, l1);
            }
#pragma unroll
            for (int j = 0; j < 4; j++) {
                sts32(smb + KV_VH + rb + 128u + 4u * j, 0x3F803F80u);
                sts32(smb + KV_VL + rb + 128u + 4u * j, 0u);
            }
        }
        __syncthreads();
        // proj: warp (wm: 32 s-rows, wn: 64 f); fused 3-pass hi/lo
        {
            float acc[2][8][4];
#pragma unroll
            for (int mt = 0; mt < 2; mt++)
#pragma unroll
                for (int nt = 0; nt < 8; nt++)
#pragma unroll
                    for (int j = 0; j < 4; j++) acc[mt][nt][j] = 0.0f;
            mma_hl2<8>(acc, smb + KV_KH + (u32)(wm * 32) * 144u,
                            smb + KV_KL + (u32)(wm * 32) * 144u,
                            smb + KV_WH + (u32)(wn * 64) * 144u,
                            smb + KV_WL + (u32)(wn * 64) * 144u, 4, 144u, 144u);
            // exp + store phi natural [s][f] pitch 272
            float n[4];
#pragma unroll
            for (int j = 0; j < 4; j++)
                n[j] = nsqs[wm * 32 + (lane >> 2) + j * 8];
#pragma unroll
            for (int nt = 0; nt < 8; nt++) {
                const int f = wn * 64 + nt * 8 + (lane & 3) * 2;
#pragma unroll
                for (int mt = 0; mt < 2; mt++) {
                    const int rb = wm * 32 + (lane >> 2) + mt * 16;
                    float p00 = __expf(acc[mt][nt][0] - n[2*mt])     * INV_SQRT_F;
                    float p01 = __expf(acc[mt][nt][1] - n[2*mt])     * INV_SQRT_F;
                    float p10 = __expf(acc[mt][nt][2] - n[2*mt + 1]) * INV_SQRT_F;
                    float p11 = __expf(acc[mt][nt][3] - n[2*mt + 1]) * INV_SQRT_F;
                    u32 hi, lo;
                    split2(p00, p01, hi, lo);
                    sts32(smb + KV_PH + (u32)rb * 272u + 2u * f, hi);
                    sts32(smb + KV_PL + (u32)rb * 272u + 2u * f, lo);
                    split2(p10, p11, hi, lo);
                    sts32(smb + KV_PH + (u32)(rb + 8) * 272u + 2u * f, hi);
                    sts32(smb + KV_PL + (u32)(rb + 8) * 272u + 2u * f, lo);
                }
            }
        }
        __syncthreads();
        // kv gemm: warp (wm: 32 f-rows, wn: 64-s k-half); trans loads
        {
            const u32 aoff = ((u32)(lane & 7) + (u32)((lane >> 4) & 1) * 8u) * 272u +
                             (u32)((lane >> 3) & 1) * 16u + (u32)(wm * 64) +
                             (u32)(wn * 64) * 272u;
            const u32 boff = ((u32)(lane & 7) + (u32)((lane >> 3) & 1) * 8u) * 144u +
                             (u32)((lane >> 4) & 1) * 16u + (u32)(wn * 64) * 144u;
            const u32 b2off = ((u32)(lane & 7) + (u32)((lane >> 3) & 1) * 8u) * 144u + 128u +
                              (u32)(wn * 64) * 144u;
            const u32 PHb = smb + KV_PH, PLb = smb + KV_PL;
            const u32 VHb = smb + KV_VH, VLb = smb + KV_VL;
            for (int kk = 0; kk < 4; kk++) {
                const u32 ka = (u32)kk * 16u * 272u, kb = (u32)kk * 16u * 144u;
                u32 ah[2][4], al[2][4];
#pragma unroll
                for (int mt = 0; mt < 2; mt++) {
                    ldsm4t(PHb + aoff + (u32)(mt * 32) + ka, ah[mt][0], ah[mt][1], ah[mt][2], ah[mt][3]);
                    ldsm4t(PLb + aoff + (u32)(mt * 32) + ka, al[mt][0], al[mt][1], al[mt][2], al[mt][3]);
                }
#pragma unroll
                for (int ntp = 0; ntp < 4; ntp++) {
                    u32 h0, h1, h2, h3, l0, l1, l2, l3;
                    ldsm4t(VHb + boff + (u32)ntp * 32u + kb, h0, h1, h2, h3);
                    ldsm4t(VLb + boff + (u32)ntp * 32u + kb, l0, l1, l2, l3);
#pragma unroll
                    for (int mt = 0; mt < 2; mt++) {
                        mma16816(kva[mt][2*ntp],   ah[mt][0], ah[mt][1], ah[mt][2], ah[mt][3], h0, h1);
                        mma16816(kva[mt][2*ntp],   ah[mt][0], ah[mt][1], ah[mt][2], ah[mt][3], l0, l1);
                        mma16816(kva[mt][2*ntp],   al[mt][0], al[mt][1], al[mt][2], al[mt][3], h0, h1);
                        mma16816(kva[mt][2*ntp+1], ah[mt][0], ah[mt][1], ah[mt][2], ah[mt][3], h2, h3);
                        mma16816(kva[mt][2*ntp+1], ah[mt][0], ah[mt][1], ah[mt][2], ah[mt][3], l2, l3);
                        mma16816(kva[mt][2*ntp+1], al[mt][0], al[mt][1], al[mt][2], al[mt][3], h2, h3);
                    }
                }
                u32 o0, o1;
                ldsm2t(VHb + b2off + kb, o0, o1);
#pragma unroll
                for (int mt = 0; mt < 2; mt++) {
                    mma16816(kva[mt][8], ah[mt][0], ah[mt][1], ah[mt][2], ah[mt][3], o0, o1);
                    mma16816(kva[mt][8], al[mt][0], al[mt][1], al[mt][2], al[mt][3], o0, o1);
                }
            }
        }
        __syncthreads();
    }
    // epilogue: scatter KV^T and ksum (k-halves merge via atomics)
#pragma unroll
    for (int mt = 0; mt < 2; mt++) {
        const int f0 = F0 + wm * 32 + (lane >> 2) + mt * 16;
#pragma unroll
        for (int nt = 0; nt < 9; nt++) {
            const int d = nt * 8 + (lane & 3) * 2;
            if (nt < 8) {
                atomicAdd(g_kvT + ((size_t)b * DD + d)     * FF + f0,      kva[mt][nt][0]);
                atomicAdd(g_kvT + ((size_t)b * DD + d + 1) * FF + f0,      kva[mt][nt][1]);
                atomicAdd(g_kvT + ((size_t)b * DD + d)     * FF + f0 + 8,  kva[mt][nt][2]);
                atomicAdd(g_kvT + ((size_t)b * DD + d + 1) * FF + f0 + 8,  kva[mt][nt][3]);
            } else if ((lane & 3) == 0) {
                atomicAdd(g_ksum + b * FF + f0,     kva[mt][nt][0]);
                atomicAdd(g_ksum + b * FF + f0 + 8, kva[mt][nt][2]);
            }
        }
    }
}

// ---------------- out: phi_q @ KV^T / deno (FA2 register passthrough) ---------
// proj C-fragments are re-packed in registers as A-fragments of the out GEMM:
// no phi smem, no per-chunk __syncthreads. INV_SQRT_F dropped (num/deno cancel).
#define OU_WH 0u
#define OU_WL 36864u
#define OU_QH 73728u
#define OU_QL 92160u
#define OU_KVH 110592u
#define OU_KVL 144384u
#define OU_KS 178176u
#define OU_DE 179200u
#define OU_SC 180224u
#define OU_SMEM (OU_SC + 33792u)
__global__ void __launch_bounds__(256, 1)
out_kernel(const float* __restrict__ q, const float* __restrict__ w, float* __restrict__ out) {
    extern __shared__ __align__(16) char sm[];
    const u32 smb = smem_u32(sm);
    const int tid = threadIdx.x, wid = tid >> 5, lane = tid & 31;
    const int wm = wid & 3, wn = wid >> 2;
    const int b = blockIdx.x;
    float* ksum_s = (float*)(sm + OU_KS);
    float* dn2    = (float*)(sm + OU_DE);   // [2][128]
    float* scr    = (float*)(sm + OU_SC);   // [128][66] f32 reduction scratch
    ksum_s[tid] = g_ksum[b * FF + tid];
    stage_row(smb + OU_WH, smb + OU_WL, (const float4*)(w + tid * DD), tid, 1.0f, 0, 0);
    if (tid >= 128) {   // KV^T tile [d][f] hi/lo, pitch 528
        const int d = (tid - 128) >> 1, half = tid & 1;
        const float* src = g_kvT + (size_t)b * DD * FF + d * FF + half * 128;
        const u32 rb = (u32)d * 528u + (u32)half * 256u;
#pragma unroll 8
        for (int j = 0; j < 64; j++) {
            u32 hi, lo;
            split2(src[2*j], src[2*j+1], hi, lo);
            sts32(smb + OU_KVH + rb + 4u * j, hi);
            sts32(smb + OU_KVL + rb + 4u * j, lo);
        }
    }

    const u32 qH = smb + OU_QH + (u32)(wm * 32) * 144u;
    const u32 qL = smb + OU_QL + (u32)(wm * 32) * 144u;
    const u32 bofK = (u32)(lane & 15) * 528u + (u32)(lane >> 4) * 16u;

    for (int tt = 0; tt < 4; tt++) {
        const int s0 = (blockIdx.y * 4 + tt) * 128;
        __syncthreads();   // prev tile consumed / staging done
        if (tid < 128)
            stage_row(smb + OU_QH, smb + OU_QL,
                      (const float4*)(q + (size_t)(b * SS + s0 + tid) * DD), tid, INV_SIGMA, 0, 0);
        __syncthreads();

        float dp[4] = {0.f, 0.f, 0.f, 0.f};
        float oacc[2][8][4];
#pragma unroll
        for (int mt = 0; mt < 2; mt++)
#pragma unroll
            for (int nt = 0; nt < 8; nt++)
#pragma unroll
                for (int j = 0; j < 4; j++) oacc[mt][nt][j] = 0.0f;

        for (int ch = 0; ch < 4; ch++) {
            // proj: warp (wm: 32 s-rows, wn: 32 f of this chunk)
            float acc[2][4][4];
#pragma unroll
            for (int mt = 0; mt < 2; mt++)
#pragma unroll
                for (int nt = 0; nt < 4; nt++)
#pragma unroll
                    for (int j = 0; j < 4; j++) acc[mt][nt][j] = 0.0f;
            mma_hl2<4>(acc, qH, qL, smb + OU_WH + (u32)(ch * 64 + wn * 32) * 144u,
                       smb + OU_WL + (u32)(ch * 64 + wn * 32) * 144u, 4, 144u, 144u);
            // per 16-f k-block: exp -> pack A frags in regs -> gemm vs KV^T
#pragma unroll
            for (int kk = 0; kk < 2; kk++) {
                u32 aH[2][4], aL[2][4];
#pragma unroll
                for (int h = 0; h < 2; h++) {
                    const int nt = kk * 2 + h;
                    const int fg = ch * 64 + wn * 32 + nt * 8 + (lane & 3) * 2;
                    const float ks0 = ksum_s[fg], ks1 = ksum_s[fg + 1];
#pragma unroll
                    for (int mt = 0; mt < 2; mt++) {
                        float p00 = __expf(acc[mt][nt][0]);
                        float p01 = __expf(acc[mt][nt][1]);
                        float p10 = __expf(acc[mt][nt][2]);
                        float p11 = __expf(acc[mt][nt][3]);
                        dp[2*mt]     += p00 * ks0 + p01 * ks1;
                        dp[2*mt + 1] += p10 * ks0 + p11 * ks1;
                        split2(p00, p01, aH[mt][2*h],     aL[mt][2*h]);
                        split2(p10, p11, aH[mt][2*h + 1], aL[mt][2*h + 1]);
                    }
                }
                const u32 kb = (u32)(ch * 128 + wn * 64 + kk * 32);
#pragma unroll
                for (int ntp = 0; ntp < 4; ntp++) {
                    u32 h0, h1, h2, h3, l0, l1, l2, l3;
                    ldsm4(smb + OU_KVH + bofK + (u32)ntp * 16u * 528u + kb, h0, h1, h2, h3);
                    ldsm4(smb + OU_KVL + bofK + (u32)ntp * 16u * 528u + kb, l0, l1, l2, l3);
#pragma unroll
                    for (int mt = 0; mt < 2; mt++) {
                        mma16816(oacc[mt][2*ntp],   aH[mt][0], aH[mt][1], aH[mt][2], aH[mt][3], h0, h2);
                        mma16816(oacc[mt][2*ntp],   aH[mt][0], aH[mt][1], aH[mt][2], aH[mt][3], l0, l2);
                        mma16816(oacc[mt][2*ntp],   aL[mt][0], aL[mt][1], aL[mt][2], aL[mt][3], h0, h2);
                        mma16816(oacc[mt][2*ntp+1], aH[mt][0], aH[mt][1], aH[mt][2], aH[mt][3], h1, h3);
                        mma16816(oacc[mt][2*ntp+1], aH[mt][0], aH[mt][1], aH[mt][2], aH[mt][3], l1, l3);
                        mma16816(oacc[mt][2*ntp+1], aL[mt][0], aL[mt][1], aL[mt][2], aL[mt][3], h1, h3);
                    }
                }
            }
        }
        // deno partials (over this warp's 32-f k-slice)
#pragma unroll
        for (int j = 0; j < 4; j++) {
            dp[j] += __shfl_xor_sync(~0u, dp[j], 1);
            dp[j] += __shfl_xor_sync(~0u, dp[j], 2);
        }
        if ((lane & 3) == 0)
#pragma unroll
            for (int j = 0; j < 4; j++)
                dn2[wn * 128 + wm * 32 + (lane >> 2) + j * 8] = dp[j];
        // reduce wn k-halves: wn1 spills oacc to scratch
        if (wn == 1) {
#pragma unroll
            for (int nt = 0; nt < 8; nt++) {
                const int d = nt * 8 + (lane & 3) * 2;
#pragma unroll
                for (int mt = 0; mt < 2; mt++) {
                    const int rb = wm * 32 + (lane >> 2) + mt * 16;
                    *(float2*)(scr + rb * 66 + d)       = make_float2(oacc[mt][nt][0], oacc[mt][nt][1]);
                    *(float2*)(scr + (rb + 8) * 66 + d) = make_float2(oacc[mt][nt][2], oacc[mt][nt][3]);
                }
            }
        }
        __syncthreads();
        if (wn == 0) {
            float inv[4];
#pragma unroll
            for (int j = 0; j < 4; j++) {
                const int r = wm * 32 + (lane >> 2) + j * 8;
                inv[j] = 1.0f / fmaxf(dn2[r] + dn2[128 + r], 1e-4f);
            }
#pragma unroll
            for (int nt = 0; nt < 8; nt++) {
                const int d = nt * 8 + (lane & 3) * 2;
#pragma unroll
                for (int mt = 0; mt < 2; mt++) {
                    const int rb = wm * 32 + (lane >> 2) + mt * 16;
                    float2 s0v = *(const float2*)(scr + rb * 66 + d);
                    float2 s1v = *(const float2*)(scr + (rb + 8) * 66 + d);
                    *(float2*)(out + (size_t)(b * SS + s0 + rb) * DD + d) =
                        make_float2((oacc[mt][nt][0] + s0v.x) * inv[2*mt],
                                    (oacc[mt][nt][1] + s0v.y) * inv[2*mt]);
                    *(float2*)(out + (size_t)(b * SS + s0 + rb + 8) * DD + d) =
                        make_float2((oacc[mt][nt][2] + s1v.x) * inv[2*mt + 1],
                                    (oacc[mt][nt][3] + s1v.y) * inv[2*mt + 1]);
                }
            }
        }
    }
}

// ---------------- launch ------------------------------------------------------
extern "C" void kernel_launch(void* const* d_in, const int* in_sizes, int n_in,
                              void* d_out, int out_size) {
    const float* q = (const float*)d_in[0];
    const float* k = (const float*)d_in[1];
    const float* v = (const float*)d_in[2];
    const float* w = (const float*)d_in[3];
    float* out = (float*)d_out;
    cudaFuncSetAttribute(kv_kernel,  cudaFuncAttributeMaxDynamicSharedMemorySize, KV_SMEM);
    cudaFuncSetAttribute(out_kernel, cudaFuncAttributeMaxDynamicSharedMemorySize, OU_SMEM);
    init_kernel<<<(BB * DD * FF + 255) / 256, 256>>>();
    mean_kernel<<<dim3(BB, 4), 256>>>(k);
    kv_kernel<<<dim3(BB, 2, 4), 256, KV_SMEM>>>(k, v, w);
    out_kernel<<<dim3(BB, 8), 256, OU_SMEM>>>(q, w, out);
}

// round 12
// speedup vs baseline: 1.6055x; 1.1987x over previous
#include <cuda_runtime.h>
#include <cuda_bf16.h>

typedef unsigned u32; typedef unsigned long long u64;
#define BB 64
#define SS 4096
#define DD 64
#define FF 256
#define INV_SIGMA 0.3535533905932738f
#define LOG2E 1.4426950408889634f
#define GRID 148

__device__ float g_mean[BB * DD];
__device__ float g_kvT [BB * DD * FF];   // [b][d][f]
__device__ float g_ksum[BB * FF];
__device__ unsigned g_bar;

// ---------------- helpers ----------------------------------------------------
__device__ __forceinline__ u32 smem_u32(const void* p) {
    u32 a; asm("{ .reg .u64 t; cvta.to.shared.u64 t, %1; cvt.u32.u64 %0, t; }" : "=r"(a) : "l"(p));
    return a;
}
__device__ __forceinline__ void sts32(u32 a, u32 v) {
    asm volatile("st.shared.b32 [%0], %1;" :: "r"(a), "r"(v) : "memory");
}
__device__ __forceinline__ float ex2f(float x) {
    float r; asm("ex2.approx.ftz.f32 %0, %1;" : "=f"(r) : "f"(x)); return r;
}
__device__ __forceinline__ void split2(float a, float b, u32& hi, u32& lo) {
    u32 h; asm("cvt.rn.bf16x2.f32 %0,%1,%2;" : "=r"(h) : "f"(b), "f"(a));
    float ah = __uint_as_float(h << 16), bh = __uint_as_float(h & 0xffff0000u);
    float ar = a - ah, br = b - bh;
    asm("cvt.rn.bf16x2.f32 %0,%1,%2;" : "=r"(lo) : "f"(br), "f"(ar));
    hi = h;
}
__device__ __forceinline__ void ldsm4(u32 a, u32& r0, u32& r1, u32& r2, u32& r3) {
    asm volatile("ldmatrix.sync.aligned.m8n8.x4.shared.b16 {%0,%1,%2,%3}, [%4];"
                 : "=r"(r0), "=r"(r1), "=r"(r2), "=r"(r3) : "r"(a));
}
__device__ __forceinline__ void ldsm4t(u32 a, u32& r0, u32& r1, u32& r2, u32& r3) {
    asm volatile("ldmatrix.sync.aligned.m8n8.x4.trans.shared.b16 {%0,%1,%2,%3}, [%4];"
                 : "=r"(r0), "=r"(r1), "=r"(r2), "=r"(r3) : "r"(a));
}
__device__ __forceinline__ void ldsm2t(u32 a, u32& r0, u32& r1) {
    asm volatile("ldmatrix.sync.aligned.m8n8.x2.trans.shared.b16 {%0,%1}, [%2];"
                 : "=r"(r0), "=r"(r1) : "r"(a));
}
__device__ __forceinline__ void mma16816(float* c, u32 a0, u32 a1, u32 a2, u32 a3, u32 b0, u32 b1) {
    asm volatile("mma.sync.aligned.m16n8k16.row.col.f32.bf16.bf16.f32 "
                 "{%0,%1,%2,%3},{%4,%5,%6,%7},{%8,%9},{%0,%1,%2,%3};"
                 : "+f"(c[0]), "+f"(c[1]), "+f"(c[2]), "+f"(c[3])
                 : "r"(a0), "r"(a1), "r"(a2), "r"(a3), "r"(b0), "r"(b1));
}

// stage one 64-float row as bf16 hi(/lo) into pitch-144B tile at row r
__device__ __forceinline__ void stage_row(u32 hB, u32 lB, const float4* src, int r, float scale,
                                          const float* cen, float* nsq_out) {
    u32 rb = (u32)r * 144u;
    float nsq = 0.0f;
#pragma unroll
    for (int i = 0; i < 16; i++) {
        float4 x = src[i];
        float c0 = x.x * scale, c1 = x.y * scale, c2 = x.z * scale, c3 = x.w * scale;
        if (cen) { c0 -= cen[4*i]; c1 -= cen[4*i+1]; c2 -= cen[4*i+2]; c3 -= cen[4*i+3]; }
        if (nsq_out) nsq += c0*c0 + c1*c1 + c2*c2 + c3*c3;
        u32 h0, l0, h1, l1;
        split2(c0, c1, h0, l0); split2(c2, c3, h1, l1);
        sts32(hB + rb + i * 8u, h0); sts32(hB + rb + i * 8u + 4u, h1);
        if (lB) { sts32(lB + rb + i * 8u, l0); sts32(lB + rb + i * 8u + 4u, l1); }
    }
    if (nsq_out) *nsq_out = 0.5f * LOG2E * nsq;
}

// 2-mtile fused hi/lo GEMM (HH + HL + LH)
template<int NT>
__device__ __forceinline__ void mma_hl2(float (&acc)[2][NT][4], u32 aH, u32 aL,
                                        u32 bH, u32 bL, int nk, u32 ap, u32 bp) {
    const int lane = threadIdx.x & 31;
    const u32 aoff = (u32)(lane & 15) * ap + (u32)(lane >> 4) * 16u;
    const u32 boff = (u32)(lane & 15) * bp + (u32)(lane >> 4) * 16u;
    for (int kk = 0; kk < nk; kk++) {
        u32 ah[2][4], al[2][4];
#pragma unroll
        for (int mt = 0; mt < 2; mt++) {
            ldsm4(aH + aoff + (u32)mt * 16u * ap + (u32)kk * 32u,
                  ah[mt][0], ah[mt][1], ah[mt][2], ah[mt][3]);
            ldsm4(aL + aoff + (u32)mt * 16u * ap + (u32)kk * 32u,
                  al[mt][0], al[mt][1], al[mt][2], al[mt][3]);
        }
#pragma unroll
        for (int ntp = 0; ntp < NT / 2; ntp++) {
            u32 h0, h1, h2, h3, l0, l1, l2, l3;
            ldsm4(bH + boff + (u32)ntp * 16u * bp + (u32)kk * 32u, h0, h1, h2, h3);
            ldsm4(bL + boff + (u32)ntp * 16u * bp + (u32)kk * 32u, l0, l1, l2, l3);
#pragma unroll
            for (int mt = 0; mt < 2; mt++) {
                mma16816(acc[mt][2*ntp],   ah[mt][0], ah[mt][1], ah[mt][2], ah[mt][3], h0, h2);
                mma16816(acc[mt][2*ntp],   ah[mt][0], ah[mt][1], ah[mt][2], ah[mt][3], l0, l2);
                mma16816(acc[mt][2*ntp],   al[mt][0], al[mt][1], al[mt][2], al[mt][3], h0, h2);
                mma16816(acc[mt][2*ntp+1], ah[mt][0], ah[mt][1], ah[mt][2], ah[mt][3], h1, h3);
                mma16816(acc[mt][2*ntp+1], ah[mt][0], ah[mt][1], ah[mt][2], ah[mt][3], l1, l3);
                mma16816(acc[mt][2*ntp+1], al[mt][0], al[mt][1], al[mt][2], al[mt][3], h1, h3);
            }
        }
    }
}

// ---------------- init + mean ------------------------------------------------
__global__ void init_kernel() {
    int i = blockIdx.x * 256 + threadIdx.x;
    if (i < BB * DD * FF) g_kvT[i] = 0.0f;
    if (i < BB * FF)      g_ksum[i] = 0.0f;
    if (i < BB * DD)      g_mean[i] = 0.0f;
    if (i == 0)           g_bar = 0u;
}
__global__ void mean_kernel(const float* __restrict__ k) {
    const int b = blockIdx.x, p = blockIdx.y;
    const int d = threadIdx.x & 63, sub = threadIdx.x >> 6;
    const float* kp = k + (size_t)(b * SS + p * 1024) * DD;
    float s = 0.0f;
    for (int r = sub; r < 1024; r += 4) s += kp[r * DD + d];
    __shared__ float sm[4][DD];
    sm[sub][d] = s; __syncthreads();
    if (threadIdx.x < DD)
        atomicAdd(&g_mean[b * DD + threadIdx.x],
                  sm[0][threadIdx.x] + sm[1][threadIdx.x] + sm[2][threadIdx.x] + sm[3][threadIdx.x]);
}

// ---------------- fused persistent kernel -------------------------------------
#define KV_WH 0u
#define KV_WL 18432u
#define KV_KH 36864u
#define KV_KL 55296u
#define KV_PH 73728u
#define KV_PL 108544u
#define KV_VH 143360u
#define KV_VL 161792u
#define KV_ME 180224u
#define KV_NS 180480u
#define FUSED_SMEM (KV_NS + 512u)
#define OU_WH 0u
#define OU_WL 36864u
#define OU_QH 73728u
#define OU_QL 92160u
#define OU_KVH 110592u
#define OU_KVL 144384u
#define OU_KS 178176u
#define OU_DE 179200u
#define OU_SC OU_QH

__device__ __forceinline__ void flush_kva(float (&kva)[2][9][4], int bh, int wm, int lane) {
    const int b = bh >> 1, F0 = (bh & 1) * 128;
#pragma unroll
    for (int mt = 0; mt < 2; mt++) {
        const int f0 = F0 + wm * 32 + (lane >> 2) + mt * 16;
#pragma unroll
        for (int nt = 0; nt < 9; nt++) {
            const int d = nt * 8 + (lane & 3) * 2;
            if (nt < 8) {
                atomicAdd(g_kvT + ((size_t)b * DD + d)     * FF + f0,      kva[mt][nt][0]);
                atomicAdd(g_kvT + ((size_t)b * DD + d + 1) * FF + f0,      kva[mt][nt][1]);
                atomicAdd(g_kvT + ((size_t)b * DD + d)     * FF + f0 + 8,  kva[mt][nt][2]);
                atomicAdd(g_kvT + ((size_t)b * DD + d + 1) * FF + f0 + 8,  kva[mt][nt][3]);
            } else if ((lane & 3) == 0) {
                atomicAdd(g_ksum + b * FF + f0,     kva[mt][nt][0]);
                atomicAdd(g_ksum + b * FF + f0 + 8, kva[mt][nt][2]);
            }
        }
    }
}

__global__ void __launch_bounds__(256, 1)
fused_kernel(const float* __restrict__ q, const float* __restrict__ k,
             const float* __restrict__ v, const float* __restrict__ w,
             float* __restrict__ out) {
    extern __shared__ __align__(16) char sm[];
    const u32 smb = smem_u32(sm);
    const int tid = threadIdx.x, wid = tid >> 5, lane = tid & 31;
    const int wm = wid & 3, wn = wid >> 2;
    const int c = blockIdx.x;

    // ================= phase 1: kv =================
    {
        float* meanc = (float*)(sm + KV_ME);
        float* nsqs  = (float*)(sm + KV_NS);
        const int u0 = (c * 2048) / GRID, u1 = ((c + 1) * 2048) / GRID;
        int curBH = -1;
        float kva[2][9][4];
#pragma unroll
        for (int mt = 0; mt < 2; mt++)
#pragma unroll
            for (int nt = 0; nt < 9; nt++)
#pragma unroll
                for (int j = 0; j < 4; j++) kva[mt][nt][j] = 0.0f;

        for (int u = u0; u < u1; u++) {
            const int bh = u >> 4, zz = u & 15;
            const int b = bh >> 1, F0 = (bh & 1) * 128;
            if (bh != curBH) {
                if (curBH != -1) {
                    flush_kva(kva, curBH, wm, lane);
#pragma unroll
                    for (int mt = 0; mt < 2; mt++)
#pragma unroll
                        for (int nt = 0; nt < 9; nt++)
#pragma unroll
                            for (int j = 0; j < 4; j++) kva[mt][nt][j] = 0.0f;
                }
                __syncthreads();   // prior unit's smem reads done before restage
                if (tid < DD) meanc[tid] = g_mean[b * DD + tid] * (INV_SIGMA / (float)SS);
                if (tid < 128)   // W scaled by LOG2E (folds exp's log2e mul)
                    stage_row(smb + KV_WH, smb + KV_WL, (const float4*)(w + (F0 + tid) * DD),
                              tid, LOG2E, 0, 0);
                __syncthreads();   // meanc/W visible before K staging reads meanc
                curBH = bh;
            }
            for (int t = 0; t < 2; t++) {
                const int s0 = (zz * 2 + t) * 128;
                if (tid < 128) {       // stage K rows (hi/lo, pitch 144)
                    float nsq;
                    stage_row(smb + KV_KH, smb + KV_KL,
                              (const float4*)(k + (size_t)(b * SS + s0 + tid) * DD),
                              tid, INV_SIGMA, meanc, &nsq);
                    nsqs[tid] = nsq;   // 0.5*LOG2E*|kc|^2
                } else {               // stage V row [s][72] + ones cols
                    const int sv = tid - 128;
                    const float4* vr = (const float4*)(v + (size_t)(b * SS + s0 + sv) * DD);
                    const u32 rb = (u32)sv * 144u;
#pragma unroll
                    for (int i = 0; i < 16; i++) {
                        float4 x = vr[i];
                        u32 h0, l0, h1, l1;
                        split2(x.x, x.y, h0, l0); split2(x.z, x.w, h1, l1);
                        sts32(smb + KV_VH + rb + i * 8u,      h0);
                        sts32(smb + KV_VH + rb + i * 8u + 4u, h1);
                        sts32(smb + KV_VL + rb + i * 8u,      l0);
                        sts32(smb + KV_VL + rb + i * 8u + 4u, l1);
                    }
#pragma unroll
                    for (int j = 0; j < 4; j++) {
                        sts32(smb + KV_VH + rb + 128u + 4u * j, 0x3F803F80u);
                        sts32(smb + KV_VL + rb + 128u + 4u * j, 0u);
                    }
                }
                __syncthreads();
                // proj: warp (wm: 32 s-rows, wn: 64 f); fused 3-pass hi/lo
                {
                    float acc[2][8][4];
#pragma unroll
                    for (int mt = 0; mt < 2; mt++)
#pragma unroll
                        for (int nt = 0; nt < 8; nt++)
#pragma unroll
                            for (int j = 0; j < 4; j++) acc[mt][nt][j] = 0.0f;
                    mma_hl2<8>(acc, smb + KV_KH + (u32)(wm * 32) * 144u,
                                    smb + KV_KL + (u32)(wm * 32) * 144u,
                                    smb + KV_WH + (u32)(wn * 64) * 144u,
                                    smb + KV_WL + (u32)(wn * 64) * 144u, 4, 144u, 144u);
                    float n[4];
#pragma unroll
                    for (int j = 0; j < 4; j++)
                        n[j] = nsqs[wm * 32 + (lane >> 2) + j * 8];
#pragma unroll
                    for (int nt = 0; nt < 8; nt++) {
                        const int f = wn * 64 + nt * 8 + (lane & 3) * 2;
#pragma unroll
                        for (int mt = 0; mt < 2; mt++) {
                            const int rb = wm * 32 + (lane >> 2) + mt * 16;
                            float p00 = ex2f(acc[mt][nt][0] - n[2*mt]);
                            float p01 = ex2f(acc[mt][nt][1] - n[2*mt]);
                            float p10 = ex2f(acc[mt][nt][2] - n[2*mt + 1]);
                            float p11 = ex2f(acc[mt][nt][3] - n[2*mt + 1]);
                            u32 hi, lo;
                            split2(p00, p01, hi, lo);
                            sts32(smb + KV_PH + (u32)rb * 272u + 2u * f, hi);
                            sts32(smb + KV_PL + (u32)rb * 272u + 2u * f, lo);
                            split2(p10, p11, hi, lo);
                            sts32(smb + KV_PH + (u32)(rb + 8) * 272u + 2u * f, hi);
                            sts32(smb + KV_PL + (u32)(rb + 8) * 272u + 2u * f, lo);
                        }
                    }
                }
                __syncthreads();
                // kv gemm: warp (wm: 32 f-rows, wn: 64-s k-half); trans loads
                {
                    const u32 aoff = ((u32)(lane & 7) + (u32)((lane >> 4) & 1) * 8u) * 272u +
                                     (u32)((lane >> 3) & 1) * 16u + (u32)(wm * 64) +
                                     (u32)(wn * 64) * 272u;
                    const u32 boff = ((u32)(lane & 7) + (u32)((lane >> 3) & 1) * 8u) * 144u +
                                     (u32)((lane >> 4) & 1) * 16u + (u32)(wn * 64) * 144u;
                    const u32 b2off = ((u32)(lane & 7) + (u32)((lane >> 3) & 1) * 8u) * 144u + 128u +
                                      (u32)(wn * 64) * 144u;
                    const u32 PHb = smb + KV_PH, PLb = smb + KV_PL;
                    const u32 VHb = smb + KV_VH, VLb = smb + KV_VL;
                    for (int kk = 0; kk < 4; kk++) {
                        const u32 ka = (u32)kk * 16u * 272u, kb = (u32)kk * 16u * 144u;
                        u32 ah[2][4], al[2][4];
#pragma unroll
                        for (int mt = 0; mt < 2; mt++) {
                            ldsm4t(PHb + aoff + (u32)(mt * 32) + ka,
                                   ah[mt][0], ah[mt][1], ah[mt][2], ah[mt][3]);
                            ldsm4t(PLb + aoff + (u32)(mt * 32) + ka,
                                   al[mt][0], al[mt][1], al[mt][2], al[mt][3]);
                        }
#pragma unroll
                        for (int ntp = 0; ntp < 4; ntp++) {
                            u32 h0, h1, h2, h3, l0, l1, l2, l3;
                            ldsm4t(VHb + boff + (u32)ntp * 32u + kb, h0, h1, h2, h3);
                            ldsm4t(VLb + boff + (u32)ntp * 32u + kb, l0, l1, l2, l3);
#pragma unroll
                            for (int mt = 0; mt < 2; mt++) {
                                mma16816(kva[mt][2*ntp],   ah[mt][0], ah[mt][1], ah[mt][2], ah[mt][3], h0, h1);
                                mma16816(kva[mt][2*ntp],   ah[mt][0], ah[mt][1], ah[mt][2], ah[mt][3], l0, l1);
                                mma16816(kva[mt][2*ntp],   al[mt][0], al[mt][1], al[mt][2], al[mt][3], h0, h1);
                                mma16816(kva[mt][2*ntp+1], ah[mt][0], ah[mt][1], ah[mt][2], ah[mt][3], h2, h3);
                                mma16816(kva[mt][2*ntp+1], ah[mt][0], ah[mt][1], ah[mt][2], ah[mt][3], l2, l3);
                                mma16816(kva[mt][2*ntp+1], al[mt][0], al[mt][1], al[mt][2], al[mt][3], h2, h3);
                            }
                        }
                        u32 o0, o1;
                        ldsm2t(VHb + b2off + kb, o0, o1);
#pragma unroll
                        for (int mt = 0; mt < 2; mt++) {
                            mma16816(kva[mt][8], ah[mt][0], ah[mt][1], ah[mt][2], ah[mt][3], o0, o1);
                            mma16816(kva[mt][8], al[mt][0], al[mt][1], al[mt][2], al[mt][3], o0, o1);
                        }
                    }
                }
                __syncthreads();
            }
        }
        if (curBH != -1) flush_kva(kva, curBH, wm, lane);
    }

    // ================= global barrier =================
    __syncthreads();
    __threadfence();
    if (tid == 0) {
        atomicAdd(&g_bar, 1u);
        while (atomicAdd(&g_bar, 0u) < (u32)GRID) __nanosleep(128);
    }
    __syncthreads();

    // ================= phase 2: out =================
    {
        float* ksum_s = (float*)(sm + OU_KS);
        float* dn2    = (float*)(sm + OU_DE);
        float* scr    = (float*)(sm + OU_SC);   // overlays Q buffers
        stage_row(smb + OU_WH, smb + OU_WL, (const float4*)(w + tid * DD),         tid,       LOG2E, 0, 0);
        stage_row(smb + OU_WH, smb + OU_WL, (const float4*)(w + (tid + 128) * DD), tid + 128, LOG2E, 0, 0);

        const int u0 = (c * 2048) / GRID, u1 = ((c + 1) * 2048) / GRID;
        int curB = -1;
        const u32 qH = smb + OU_QH + (u32)(wm * 32) * 144u;
        const u32 qL = smb + OU_QL + (u32)(wm * 32) * 144u;
        const u32 bofK = (u32)(lane & 15) * 528u + (u32)(lane >> 4) * 16u;

        for (int u = u0; u < u1; u++) {
            const int b = u >> 5, s0 = (u & 31) * 128;
            __syncthreads();   // prev unit's smem reads done / W staging done
            if (b != curB) {
                ksum_s[tid] = __ldcg(g_ksum + b * FF + tid);
                const int d = tid >> 2, qf = tid & 3;
                const float* src = g_kvT + (size_t)b * DD * FF + d * FF + qf * 64;
                const u32 rb = (u32)d * 528u + (u32)qf * 128u;
#pragma unroll 8
                for (int j = 0; j < 32; j++) {
                    u32 hi, lo;
                    split2(__ldcg(src + 2*j), __ldcg(src + 2*j + 1), hi, lo);
                    sts32(smb + OU_KVH + rb + 4u * j, hi);
                    sts32(smb + OU_KVL + rb + 4u * j, lo);
                }
                curB = b;
            }
            if (tid < 128)
                stage_row(smb + OU_QH, smb + OU_QL,
                          (const float4*)(q + (size_t)(b * SS + s0 + tid) * DD), tid, INV_SIGMA, 0, 0);
            __syncthreads();

            float dp[4] = {0.f, 0.f, 0.f, 0.f};
            float oacc[2][8][4];
#pragma unroll
            for (int mt = 0; mt < 2; mt++)
#pragma unroll
                for (int nt = 0; nt < 8; nt++)
#pragma unroll
                    for (int j = 0; j < 4; j++) oacc[mt][nt][j] = 0.0f;

            for (int ch = 0; ch < 4; ch++) {
                float acc[2][4][4];
#pragma unroll
                for (int mt = 0; mt < 2; mt++)
#pragma unroll
                    for (int nt = 0; nt < 4; nt++)
#pragma unroll
                        for (int j = 0; j < 4; j++) acc[mt][nt][j] = 0.0f;
                mma_hl2<4>(acc, qH, qL, smb + OU_WH + (u32)(ch * 64 + wn * 32) * 144u,
                           smb + OU_WL + (u32)(ch * 64 + wn * 32) * 144u, 4, 144u, 144u);
#pragma unroll
                for (int kk = 0; kk < 2; kk++) {
                    u32 aH[2][4], aL[2][4];
#pragma unroll
                    for (int h = 0; h < 2; h++) {
                        const int nt = kk * 2 + h;
                        const int fg = ch * 64 + wn * 32 + nt * 8 + (lane & 3) * 2;
                        const float ks0 = ksum_s[fg], ks1 = ksum_s[fg + 1];
#pragma unroll
                        for (int mt = 0; mt < 2; mt++) {
                            float p00 = ex2f(acc[mt][nt][0]);
                            float p01 = ex2f(acc[mt][nt][1]);
                            float p10 = ex2f(acc[mt][nt][2]);
                            float p11 = ex2f(acc[mt][nt][3]);
                            dp[2*mt]     += p00 * ks0 + p01 * ks1;
                            dp[2*mt + 1] += p10 * ks0 + p11 * ks1;
                            split2(p00, p01, aH[mt][2*h],     aL[mt][2*h]);
                            split2(p10, p11, aH[mt][2*h + 1], aL[mt][2*h + 1]);
                        }
                    }
                    const u32 kb = (u32)(ch * 128 + wn * 64 + kk * 32);
#pragma unroll
                    for (int ntp = 0; ntp < 4; ntp++) {
                        u32 h0, h1, h2, h3, l0, l1, l2, l3;
                        ldsm4(smb + OU_KVH + bofK + (u32)ntp * 16u * 528u + kb, h0, h1, h2, h3);
                        ldsm4(smb + OU_KVL + bofK + (u32)ntp * 16u * 528u + kb, l0, l1, l2, l3);
#pragma unroll
                        for (int mt = 0; mt < 2; mt++) {
                            mma16816(oacc[mt][2*ntp],   aH[mt][0], aH[mt][1], aH[mt][2], aH[mt][3], h0, h2);
                            mma16816(oacc[mt][2*ntp],   aH[mt][0], aH[mt][1], aH[mt][2], aH[mt][3], l0, l2);
                            mma16816(oacc[mt][2*ntp],   aL[mt][0], aL[mt][1], aL[mt][2], aL[mt][3], h0, h2);
                            mma16816(oacc[mt][2*ntp+1], aH[mt][0], aH[mt][1], aH[mt][2], aH[mt][3], h1, h3);
                            mma16816(oacc[mt][2*ntp+1], aH[mt][0], aH[mt][1], aH[mt][2], aH[mt][3], l1, l3);
                            mma16816(oacc[mt][2*ntp+1], aL[mt][0], aL[mt][1], aL[mt][2], aL[mt][3], h1, h3);
                        }
                    }
                }
            }
#pragma unroll
            for (int j = 0; j < 4; j++) {
                dp[j] += __shfl_xor_sync(~0u, dp[j], 1);
                dp[j] += __shfl_xor_sync(~0u, dp[j], 2);
            }
            if ((lane & 3) == 0)
#pragma unroll
                for (int j = 0; j < 4; j++)
                    dn2[wn * 128 + wm * 32 + (lane >> 2) + j * 8] = dp[j];
            if (wn == 1) {
#pragma unroll
                for (int nt = 0; nt < 8; nt++) {
                    const int d = nt * 8 + (lane & 3) * 2;
#pragma unroll
                    for (int mt = 0; mt < 2; mt++) {
                        const int rb = wm * 32 + (lane >> 2) + mt * 16;
                        *(float2*)(scr + rb * 66 + d)       = make_float2(oacc[mt][nt][0], oacc[mt][nt][1]);
                        *(float2*)(scr + (rb + 8) * 66 + d) = make_float2(oacc[mt][nt][2], oacc[mt][nt][3]);
                    }
                }
            }
            __syncthreads();
            if (wn == 0) {
                float inv[4];
#pragma unroll
                for (int j = 0; j < 4; j++) {
                    const int r = wm * 32 + (lane >> 2) + j * 8;
                    inv[j] = 1.0f / fmaxf(dn2[r] + dn2[128 + r], 1e-4f);
                }
#pragma unroll
                for (int nt = 0; nt < 8; nt++) {
                    const int d = nt * 8 + (lane & 3) * 2;
#pragma unroll
                    for (int mt = 0; mt < 2; mt++) {
                        const int rb = wm * 32 + (lane >> 2) + mt * 16;
                        float2 s0v = *(const float2*)(scr + rb * 66 + d);
                        float2 s1v = *(const float2*)(scr + (rb + 8) * 66 + d);
                        *(float2*)(out + (size_t)(b * SS + s0 + rb) * DD + d) =
                            make_float2((oacc[mt][nt][0] + s0v.x) * inv[2*mt],
                                        (oacc[mt][nt][1] + s0v.y) * inv[2*mt]);
                        *(float2*)(out + (size_t)(b * SS + s0 + rb + 8) * DD + d) =
                            make_float2((oacc[mt][nt][2] + s1v.x) * inv[2*mt + 1],
                                        (oacc[mt][nt][3] + s1v.y) * inv[2*mt + 1]);
                    }
                }
            }
        }
    }
}

// ---------------- launch ------------------------------------------------------
extern "C" void kernel_launch(void* const* d_in, const int* in_sizes, int n_in,
                              void* d_out, int out_size) {
    const float* q = (const float*)d_in[0];
    const float* k = (const float*)d_in[1];
    const float* v = (const float*)d_in[2];
    const float* w = (const float*)d_in[3];
    float* out = (float*)d_out;
    cudaFuncSetAttribute(fused_kernel, cudaFuncAttributeMaxDynamicSharedMemorySize, FUSED_SMEM);
    init_kernel<<<(BB * DD * FF + 255) / 256, 256>>>();
    mean_kernel<<<dim3(BB, 4), 256>>>(k);
    fused_kernel<<<GRID, 256, FUSED_SMEM>>>(q, k, v, w, out);
}